// round 1
// baseline (speedup 1.0000x reference)
#include <cuda_runtime.h>
#include <math.h>

#define B_    2
#define S_    4096
#define HID_  2048
#define NH_   16
#define HD_   128
#define RD_   64
#define RATIO_ 4
#define NW_   (S_/RATIO_)     /* 1024 */
#define MS_   (B_*S_)         /* 8192 */
#define QN_   (NH_*HD_)       /* 2048 */

#define BQ    64
#define BKT   64
#define QSTR  132
#define SSTR  68

// ---------------- scratch (static device allocations) ----------------
__device__ float g_q_lin[(size_t)MS_*QN_];
__device__ float g_q_rot[(size_t)MS_*QN_];    // [B][NH][S][HD], pre-scaled
__device__ float g_kv  [(size_t)MS_*2*HD_];
__device__ float g_gate[(size_t)MS_*2*HD_];
__device__ float g_v   [(size_t)B_*NW_*HD_];
__device__ float g_krot[(size_t)B_*NW_*HD_];
__device__ float g_attn[(size_t)MS_*QN_];     // [B][S][NH*HD]

// ---------------- classic 128x128x8 SGEMM, C = A[MxK] @ B[KxN] ----------------
__global__ __launch_bounds__(256) void sgemm128(
    const float* __restrict__ A, const float* __restrict__ Bm,
    float* __restrict__ C, int M, int N, int K)
{
    __shared__ float As[8][128];
    __shared__ float Bs[8][128];
    int tid = threadIdx.x;
    int tx = tid & 15, ty = tid >> 4;
    int rowBase = blockIdx.y * 128;
    int colBase = blockIdx.x * 128;
    int aRow = tid >> 1;
    int aCol = (tid & 1) * 4;
    int bRow = tid >> 5;
    int bCol = (tid & 31) * 4;
    const float* Aptr = A + (size_t)(rowBase + aRow) * K + aCol;
    const float* Bptr = Bm + (size_t)bRow * N + colBase + bCol;

    float acc[8][8];
#pragma unroll
    for (int i = 0; i < 8; i++)
#pragma unroll
        for (int j = 0; j < 8; j++) acc[i][j] = 0.f;

    for (int k0 = 0; k0 < K; k0 += 8) {
        float4 av = *(const float4*)(Aptr + k0);
        As[aCol+0][aRow] = av.x; As[aCol+1][aRow] = av.y;
        As[aCol+2][aRow] = av.z; As[aCol+3][aRow] = av.w;
        *(float4*)&Bs[bRow][bCol] = *(const float4*)(Bptr + (size_t)k0 * N);
        __syncthreads();
#pragma unroll
        for (int k = 0; k < 8; k++) {
            float ra[8], rb[8];
            *(float4*)&ra[0] = *(float4*)&As[k][ty*8];
            *(float4*)&ra[4] = *(float4*)&As[k][ty*8+4];
            *(float4*)&rb[0] = *(float4*)&Bs[k][tx*8];
            *(float4*)&rb[4] = *(float4*)&Bs[k][tx*8+4];
#pragma unroll
            for (int i = 0; i < 8; i++)
#pragma unroll
                for (int j = 0; j < 8; j++)
                    acc[i][j] += ra[i] * rb[j];
        }
        __syncthreads();
    }
#pragma unroll
    for (int i = 0; i < 8; i++) {
        float* cp = C + (size_t)(rowBase + ty*8 + i) * N + colBase + tx*8;
        *(float4*)cp       = make_float4(acc[i][0], acc[i][1], acc[i][2], acc[i][3]);
        *(float4*)(cp + 4) = make_float4(acc[i][4], acc[i][5], acc[i][6], acc[i][7]);
    }
}

// ---------------- overlap-pool + K-RoPE (thread per (b, window, dim-pair)) ----------------
__global__ void pool_kernel(const float* __restrict__ kv, const float* __restrict__ gate,
                            const float* __restrict__ ape,
                            float* __restrict__ v, float* __restrict__ krot)
{
    int idx = blockIdx.x * blockDim.x + threadIdx.x;  // B*NW*64
    if (idx >= B_*NW_*64) return;
    int p = idx & 63;
    int w = (idx >> 6) % NW_;
    int b = idx / (64 * NW_);
    int d0 = 2 * p;

    const float* kvb = kv   + (size_t)b * S_ * 2 * HD_;
    const float* gb  = gate + (size_t)b * S_ * 2 * HD_;

    float kvv[8][2], gv[8][2];
#pragma unroll
    for (int j = 0; j < RATIO_; j++) {
        if (w > 0) {
            int t = (w - 1) * RATIO_ + j;
            float2 kk = *(const float2*)&kvb[(size_t)t * 2 * HD_ + d0];
            float2 gg = *(const float2*)&gb [(size_t)t * 2 * HD_ + d0];
            float2 aa = *(const float2*)&ape[(size_t)j * 2 * HD_ + d0];
            kvv[j][0] = kk.x;        kvv[j][1] = kk.y;
            gv [j][0] = gg.x + aa.x; gv [j][1] = gg.y + aa.y;
        } else {
            kvv[j][0] = kvv[j][1] = 0.f;
            gv [j][0] = gv [j][1] = -1e30f;
        }
        int t2 = w * RATIO_ + j;
        float2 kk2 = *(const float2*)&kvb[(size_t)t2 * 2 * HD_ + HD_ + d0];
        float2 gg2 = *(const float2*)&gb [(size_t)t2 * 2 * HD_ + HD_ + d0];
        float2 aa2 = *(const float2*)&ape[(size_t)j * 2 * HD_ + HD_ + d0];
        kvv[4+j][0] = kk2.x;         kvv[4+j][1] = kk2.y;
        gv [4+j][0] = gg2.x + aa2.x; gv [4+j][1] = gg2.y + aa2.y;
    }

    float out2[2];
#pragma unroll
    for (int c = 0; c < 2; c++) {
        float m = -1e30f;
#pragma unroll
        for (int j = 0; j < 8; j++) m = fmaxf(m, gv[j][c]);
        float s = 0.f, acc = 0.f;
#pragma unroll
        for (int j = 0; j < 8; j++) {
            float e = __expf(gv[j][c] - m);
            s += e; acc += e * kvv[j][c];
        }
        out2[c] = acc / s;
    }

    float* vp = v + ((size_t)b * NW_ + w) * HD_ + d0;
    *(float2*)vp = make_float2(out2[0], out2[1]);

    float y0 = out2[0], y1 = out2[1];
    if (p >= 32) {
        int i = p - 32;
        float inv = (float)pow(10000.0, -(double)i / 32.0);
        float ang = (float)(w * RATIO_) * inv;
        float sn, c;
        sincosf(ang, &sn, &c);
        y0 = out2[0] * c - out2[1] * sn;
        y1 = out2[0] * sn + out2[1] * c;
    }
    float* kp = krot + ((size_t)b * NW_ + w) * HD_ + d0;
    *(float2*)kp = make_float2(y0, y1);
}

// ---------------- Q RoPE + transpose to [B][NH][S][HD], pre-scaled by 1/sqrt(HD) ----------------
__global__ void rope_q_kernel(const float* __restrict__ qlin, float* __restrict__ qrot)
{
    int idx = blockIdx.x * blockDim.x + threadIdx.x;   // MS_*NH_*64
    if (idx >= MS_ * NH_ * 64) return;
    int p  = idx & 63;
    int h  = (idx >> 6) % NH_;
    int bs = idx / (64 * NH_);
    int b = bs / S_, s = bs % S_;

    const float2 xv = *(const float2*)(qlin + (size_t)bs * QN_ + h * HD_ + 2 * p);
    float y0 = xv.x, y1 = xv.y;
    if (p >= 32) {
        int i = p - 32;
        float inv = (float)pow(10000.0, -(double)i / 32.0);
        float ang = (float)s * inv;
        float sn, c;
        sincosf(ang, &sn, &c);
        y0 = xv.x * c - xv.y * sn;
        y1 = xv.x * sn + xv.y * c;
    }
    const float scale = 0.08838834764831845f;  // 128^-0.5
    float* dst = qrot + (((size_t)b * NH_ + h) * S_ + s) * HD_ + 2 * p;
    *(float2*)dst = make_float2(y0 * scale, y1 * scale);
}

// ---------------- flash attention with sink, MQA-style shared K/V ----------------
__global__ __launch_bounds__(256) void attn_kernel(
    const float* __restrict__ qrot,  // [B][NH][S][HD] (pre-scaled)
    const float* __restrict__ krot,  // [B][NW][HD]
    const float* __restrict__ vv,    // [B][NW][HD]
    const float* __restrict__ sinks, // [NH]
    float* __restrict__ out)         // [B][S][NH*HD]
{
    extern __shared__ float sm[];
    float* Qs    = sm;
    float* Ks    = Qs + BQ * QSTR;
    float* Vs    = Ks + BQ * QSTR;
    float* Ss    = Vs + BQ * QSTR;       // [BQ][SSTR]
    float* rowm  = Ss + BQ * SSTR;
    float* rowl  = rowm + BQ;
    float* rowsc = rowl + BQ;

    int tid = threadIdx.x;
    int b = blockIdx.z, h = blockIdx.y;
    int q0 = blockIdx.x * BQ;
    int ty = tid >> 4, tx = tid & 15;

    // load Q tile
    const float* qsrc = qrot + (((size_t)b * NH_ + h) * S_ + q0) * HD_;
#pragma unroll
    for (int t = 0; t < 8; t++) {
        int lin = tid + t * 256;           // 0..2047
        int row = lin >> 5, c4 = (lin & 31) * 4;
        *(float4*)&Qs[row * QSTR + c4] = *(const float4*)&qsrc[(size_t)row * HD_ + c4];
    }
    if (tid < BQ) { rowm[tid] = -1e30f; rowl[tid] = 0.f; }

    float o[4][8];
#pragma unroll
    for (int i = 0; i < 4; i++)
#pragma unroll
        for (int c = 0; c < 8; c++) o[i][c] = 0.f;

    int kmax = (q0 + BQ - 4) >> 2;       // last window with any valid q in tile
    if (kmax > NW_ - 1) kmax = NW_ - 1;
    int nkt = kmax / BKT + 1;

    const float* kb = krot + (size_t)b * NW_ * HD_;
    const float* vb = vv   + (size_t)b * NW_ * HD_;

    for (int kt = 0; kt < nkt; kt++) {
        __syncthreads();
        // load K, V tiles
#pragma unroll
        for (int t = 0; t < 8; t++) {
            int lin = tid + t * 256;
            int row = lin >> 5, c4 = (lin & 31) * 4;
            *(float4*)&Ks[row * QSTR + c4] = *(const float4*)&kb[(size_t)(kt * BKT + row) * HD_ + c4];
            *(float4*)&Vs[row * QSTR + c4] = *(const float4*)&vb[(size_t)(kt * BKT + row) * HD_ + c4];
        }
        __syncthreads();

        // S = Q K^T  (q rows ty*4+i, k cols tx+16j)
        float acc[4][4];
#pragma unroll
        for (int i = 0; i < 4; i++)
#pragma unroll
            for (int j = 0; j < 4; j++) acc[i][j] = 0.f;

        for (int d = 0; d < HD_; d += 4) {
            float4 qa[4], ka[4];
#pragma unroll
            for (int i = 0; i < 4; i++) qa[i] = *(float4*)&Qs[(ty*4+i) * QSTR + d];
#pragma unroll
            for (int j = 0; j < 4; j++) ka[j] = *(float4*)&Ks[(tx + 16*j) * QSTR + d];
#pragma unroll
            for (int i = 0; i < 4; i++)
#pragma unroll
                for (int j = 0; j < 4; j++) {
                    acc[i][j] += qa[i].x * ka[j].x;
                    acc[i][j] += qa[i].y * ka[j].y;
                    acc[i][j] += qa[i].z * ka[j].z;
                    acc[i][j] += qa[i].w * ka[j].w;
                }
        }
#pragma unroll
        for (int i = 0; i < 4; i++)
#pragma unroll
            for (int j = 0; j < 4; j++) {
                int qg = q0 + ty*4 + i;
                int kg = kt * BKT + tx + 16*j;
                float sv = (qg >= 4*kg + 3) ? acc[i][j] : -1e30f;
                Ss[(ty*4+i) * SSTR + tx + 16*j] = sv;
            }
        __syncthreads();

        // online softmax update (4 threads per row)
        {
            int r = tid >> 2, j = tid & 3;
            float mx = -1e30f;
            for (int k = j; k < BKT; k += 4) mx = fmaxf(mx, Ss[r * SSTR + k]);
            mx = fmaxf(mx, __shfl_xor_sync(0xffffffffu, mx, 1));
            mx = fmaxf(mx, __shfl_xor_sync(0xffffffffu, mx, 2));
            float mold = rowm[r];
            float mnew = fmaxf(mold, mx);
            float ssum = 0.f;
            for (int k = j; k < BKT; k += 4) {
                float pe = __expf(Ss[r * SSTR + k] - mnew);
                Ss[r * SSTR + k] = pe;
                ssum += pe;
            }
            ssum += __shfl_xor_sync(0xffffffffu, ssum, 1);
            ssum += __shfl_xor_sync(0xffffffffu, ssum, 2);
            if (j == 0) {
                float sc = __expf(mold - mnew);
                rowsc[r] = sc;
                rowl[r] = rowl[r] * sc + ssum;
                rowm[r] = mnew;
            }
        }
        __syncthreads();

        // O = O*sc + P V   (q rows ty*4+i, d cols tx*8..+7)
#pragma unroll
        for (int i = 0; i < 4; i++) {
            float sc = rowsc[ty*4 + i];
#pragma unroll
            for (int c = 0; c < 8; c++) o[i][c] *= sc;
        }
        for (int k = 0; k < BKT; k++) {
            float4 v0 = *(float4*)&Vs[k * QSTR + tx*8];
            float4 v1 = *(float4*)&Vs[k * QSTR + tx*8 + 4];
#pragma unroll
            for (int i = 0; i < 4; i++) {
                float pe = Ss[(ty*4+i) * SSTR + k];
                o[i][0] += pe * v0.x; o[i][1] += pe * v0.y;
                o[i][2] += pe * v0.z; o[i][3] += pe * v0.w;
                o[i][4] += pe * v1.x; o[i][5] += pe * v1.y;
                o[i][6] += pe * v1.z; o[i][7] += pe * v1.w;
            }
        }
    }
    __syncthreads();

    // finalize: fold in sink column, compute 1/l
    if (tid < BQ) {
        float sh = sinks[h];
        float mold = rowm[tid];
        float mf = fmaxf(mold, sh);
        float lf = rowl[tid] * __expf(mold - mf) + __expf(sh - mf);
        rowsc[tid] = __expf(mold - mf) / lf;
    }
    __syncthreads();

#pragma unroll
    for (int i = 0; i < 4; i++) {
        int qg = q0 + ty*4 + i;
        float sc = rowsc[ty*4 + i];
        float* dst = out + ((size_t)b * S_ + qg) * QN_ + h * HD_ + tx*8;
        *(float4*)dst       = make_float4(o[i][0]*sc, o[i][1]*sc, o[i][2]*sc, o[i][3]*sc);
        *(float4*)(dst + 4) = make_float4(o[i][4]*sc, o[i][5]*sc, o[i][6]*sc, o[i][7]*sc);
    }
}

// ---------------- launch ----------------
extern "C" void kernel_launch(void* const* d_in, const int* in_sizes, int n_in,
                              void* d_out, int out_size)
{
    const float* hidden = (const float*)d_in[0];
    const float* wq     = (const float*)d_in[1];
    const float* wkv    = (const float*)d_in[2];
    const float* wgate  = (const float*)d_in[3];
    const float* ape    = (const float*)d_in[4];
    const float* sinks  = (const float*)d_in[5];
    const float* wo     = (const float*)d_in[6];
    float* out = (float*)d_out;

    float *qlin, *qrot, *kvb, *gb, *vb, *krot, *attn;
    cudaGetSymbolAddress((void**)&qlin, g_q_lin);
    cudaGetSymbolAddress((void**)&qrot, g_q_rot);
    cudaGetSymbolAddress((void**)&kvb,  g_kv);
    cudaGetSymbolAddress((void**)&gb,   g_gate);
    cudaGetSymbolAddress((void**)&vb,   g_v);
    cudaGetSymbolAddress((void**)&krot, g_krot);
    cudaGetSymbolAddress((void**)&attn, g_attn);

    // projections
    sgemm128<<<dim3(2*HD_/128, MS_/128), 256>>>(hidden, wkv,   kvb,  MS_, 2*HD_, HID_);
    sgemm128<<<dim3(2*HD_/128, MS_/128), 256>>>(hidden, wgate, gb,   MS_, 2*HD_, HID_);
    sgemm128<<<dim3(QN_/128,   MS_/128), 256>>>(hidden, wq,    qlin, MS_, QN_,   HID_);

    // pool + K rope; Q rope + transpose
    pool_kernel<<<(B_*NW_*64 + 255)/256, 256>>>(kvb, gb, ape, vb, krot);
    rope_q_kernel<<<(MS_*NH_*64 + 255)/256, 256>>>(qlin, qrot);

    // attention
    size_t shmem = (size_t)(3*BQ*QSTR + BQ*SSTR + 3*BQ) * sizeof(float);
    cudaFuncSetAttribute(attn_kernel, cudaFuncAttributeMaxDynamicSharedMemorySize, (int)shmem);
    attn_kernel<<<dim3(S_/BQ, NH_, B_), 256, shmem>>>(qrot, krot, vb, sinks, attn);

    // output projection
    sgemm128<<<dim3(QN_/128, MS_/128), 256>>>(attn, wo, out, MS_, QN_, HID_);
}

// round 3
// speedup vs baseline: 1.5872x; 1.5872x over previous
#include <cuda_runtime.h>
#include <cuda_fp16.h>
#include <math.h>

#define B_     2
#define S_     4096
#define HID_   2048
#define NH_    16
#define HD_    128
#define RATIO_ 4
#define NW_    1024
#define MS_    8192
#define QN_    2048

#define BQ    64
#define BKT   64
#define QSTR  132
#define SSTR  68

#define GBM 128
#define GBN 128
#define GBK 32
#define APAD 8
#define BPAD 8

// ---------------- scratch (static device allocations) ----------------
__device__ float g_q_lin[(size_t)MS_ * QN_];
__device__ float g_q_rot[(size_t)MS_ * QN_];
__device__ float g_kv[(size_t)MS_ * 2 * HD_];
__device__ float g_gate[(size_t)MS_ * 2 * HD_];
__device__ float g_v[(size_t)B_ * NW_ * HD_];
__device__ float g_krot[(size_t)B_ * NW_ * HD_];

__device__ unsigned short g_h_hidden[(size_t)MS_ * HID_];
__device__ unsigned short g_h_wq[(size_t)HID_ * QN_];
__device__ unsigned short g_h_wkv[(size_t)HID_ * 2 * HD_];
__device__ unsigned short g_h_wgate[(size_t)HID_ * 2 * HD_];
__device__ unsigned short g_h_wo[(size_t)QN_ * HID_];
__device__ unsigned short g_h_attn[(size_t)MS_ * QN_];

// ---------------- fp32 -> fp16 ----------------
__global__ void f2h_kernel(const float4* __restrict__ in, __half2* __restrict__ out, int n4)
{
    int i = blockIdx.x * blockDim.x + threadIdx.x;
    if (i < n4) {
        float4 v = in[i];
        out[2 * i] = __floats2half2_rn(v.x, v.y);
        out[2 * i + 1] = __floats2half2_rn(v.z, v.w);
    }
}

// ---------------- PTX helpers ----------------
__device__ __forceinline__ void cp16(void* dst, const void* src)
{
    unsigned d = (unsigned)__cvta_generic_to_shared(dst);
    asm volatile("cp.async.cg.shared.global [%0], [%1], 16;" :: "r"(d), "l"(src));
}

__device__ __forceinline__ void cp_commit()
{
    asm volatile("cp.async.commit_group;");
}

__device__ __forceinline__ void cp_wait1()
{
    asm volatile("cp.async.wait_group 1;");
}

__device__ __forceinline__ void cp_wait0()
{
    asm volatile("cp.async.wait_group 0;");
}

__device__ __forceinline__ void ldm_x4(unsigned* r, const void* p)
{
    unsigned a = (unsigned)__cvta_generic_to_shared(p);
    asm volatile("ldmatrix.sync.aligned.m8n8.x4.shared.b16 {%0,%1,%2,%3}, [%4];"
                 : "=r"(r[0]), "=r"(r[1]), "=r"(r[2]), "=r"(r[3]) : "r"(a));
}

__device__ __forceinline__ void ldm_x4_t(unsigned* r, const void* p)
{
    unsigned a = (unsigned)__cvta_generic_to_shared(p);
    asm volatile("ldmatrix.sync.aligned.m8n8.x4.trans.shared.b16 {%0,%1,%2,%3}, [%4];"
                 : "=r"(r[0]), "=r"(r[1]), "=r"(r[2]), "=r"(r[3]) : "r"(a));
}

__device__ __forceinline__ void mma16816(float* c, const unsigned* a, unsigned b0, unsigned b1)
{
    asm volatile("mma.sync.aligned.m16n8k16.row.col.f32.f16.f16.f32 "
                 "{%0,%1,%2,%3},{%4,%5,%6,%7},{%8,%9},{%0,%1,%2,%3};"
                 : "+f"(c[0]), "+f"(c[1]), "+f"(c[2]), "+f"(c[3])
                 : "r"(a[0]), "r"(a[1]), "r"(a[2]), "r"(a[3]), "r"(b0), "r"(b1));
}

// ---------------- 128x128x32 fp16 tensor-core GEMM ----------------
__global__ __launch_bounds__(256) void hgemm(
    const __half* __restrict__ A, const __half* __restrict__ Bm,
    float* __restrict__ C, int M, int N, int K)
{
    __shared__ __half As[2][GBM][GBK + APAD];
    __shared__ __half Bs[2][GBK][GBN + BPAD];

    int tid = threadIdx.x;
    int lane = tid & 31;
    int wid = tid >> 5;
    int warpM = wid & 3;
    int warpN = wid >> 2;
    int rowBase = blockIdx.y * GBM;
    int colBase = blockIdx.x * GBN;

    float acc[2][8][4];
    for (int i = 0; i < 2; i++)
        for (int j = 0; j < 8; j++)
            for (int c = 0; c < 4; c++)
                acc[i][j][c] = 0.f;

    int arow = tid >> 2;
    int acol = (tid & 3) * 8;
    int brow = tid >> 4;
    int bcol = (tid & 15) * 8;

    const __half* Ag0 = A + (size_t)(rowBase + arow) * K + acol;
    const __half* Bg0 = Bm + (size_t)brow * N + colBase + bcol;

    int T = K / GBK;

    cp16(&As[0][arow][acol], Ag0);
    cp16(&As[0][arow + 64][acol], Ag0 + (size_t)64 * K);
    cp16(&Bs[0][brow][bcol], Bg0);
    cp16(&Bs[0][brow + 16][bcol], Bg0 + (size_t)16 * N);
    cp_commit();

    for (int t = 0; t < T; t++) {
        int s = t & 1;
        if (t + 1 < T) {
            const __half* Ag = Ag0 + (size_t)(t + 1) * GBK;
            const __half* Bg = Bg0 + (size_t)(t + 1) * GBK * N;
            cp16(&As[s ^ 1][arow][acol], Ag);
            cp16(&As[s ^ 1][arow + 64][acol], Ag + (size_t)64 * K);
            cp16(&Bs[s ^ 1][brow][bcol], Bg);
            cp16(&Bs[s ^ 1][brow + 16][bcol], Bg + (size_t)16 * N);
            cp_commit();
            cp_wait1();
        } else {
            cp_wait0();
        }
        __syncthreads();

#pragma unroll
        for (int kk = 0; kk < GBK; kk += 16) {
            unsigned afr[2][4];
            unsigned bfr[4][4];
#pragma unroll
            for (int i = 0; i < 2; i++) {
                ldm_x4(afr[i], &As[s][warpM * 32 + i * 16 + (lane & 15)][kk + (lane >> 4) * 8]);
            }
#pragma unroll
            for (int j = 0; j < 4; j++) {
                ldm_x4_t(bfr[j], &Bs[s][kk + ((lane >> 3) & 1) * 8 + (lane & 7)][warpN * 64 + j * 16 + (lane >> 4) * 8]);
            }
#pragma unroll
            for (int i = 0; i < 2; i++) {
#pragma unroll
                for (int j = 0; j < 4; j++) {
                    mma16816(acc[i][2 * j], afr[i], bfr[j][0], bfr[j][1]);
                    mma16816(acc[i][2 * j + 1], afr[i], bfr[j][2], bfr[j][3]);
                }
            }
        }
        __syncthreads();
    }

    int r0 = rowBase + warpM * 32 + (lane >> 2);
    int c0 = colBase + warpN * 64 + (lane & 3) * 2;
#pragma unroll
    for (int i = 0; i < 2; i++) {
#pragma unroll
        for (int j = 0; j < 8; j++) {
            float2* p0 = (float2*)&C[(size_t)(r0 + i * 16) * N + c0 + j * 8];
            p0[0] = make_float2(acc[i][j][0], acc[i][j][1]);
            float2* p1 = (float2*)&C[(size_t)(r0 + i * 16 + 8) * N + c0 + j * 8];
            p1[0] = make_float2(acc[i][j][2], acc[i][j][3]);
        }
    }
}

// ---------------- overlap-pool + K-RoPE ----------------
__global__ void pool_kernel(const float* __restrict__ ape)
{
    int idx = blockIdx.x * blockDim.x + threadIdx.x;
    if (idx >= B_ * NW_ * 64) return;
    int p = idx & 63;
    int w = (idx >> 6) % NW_;
    int b = idx / (64 * NW_);
    int d0 = 2 * p;

    const float* kvb = g_kv + (size_t)b * S_ * 2 * HD_;
    const float* gb = g_gate + (size_t)b * S_ * 2 * HD_;

    float kvv[8][2];
    float gv[8][2];
#pragma unroll
    for (int j = 0; j < RATIO_; j++) {
        if (w > 0) {
            int t = (w - 1) * RATIO_ + j;
            float2 kk = *(const float2*)&kvb[(size_t)t * 2 * HD_ + d0];
            float2 gg = *(const float2*)&gb[(size_t)t * 2 * HD_ + d0];
            float2 aa = *(const float2*)&ape[(size_t)j * 2 * HD_ + d0];
            kvv[j][0] = kk.x;
            kvv[j][1] = kk.y;
            gv[j][0] = gg.x + aa.x;
            gv[j][1] = gg.y + aa.y;
        } else {
            kvv[j][0] = 0.f;
            kvv[j][1] = 0.f;
            gv[j][0] = -1e30f;
            gv[j][1] = -1e30f;
        }
        int t2 = w * RATIO_ + j;
        float2 kk2 = *(const float2*)&kvb[(size_t)t2 * 2 * HD_ + HD_ + d0];
        float2 gg2 = *(const float2*)&gb[(size_t)t2 * 2 * HD_ + HD_ + d0];
        float2 aa2 = *(const float2*)&ape[(size_t)j * 2 * HD_ + HD_ + d0];
        kvv[4 + j][0] = kk2.x;
        kvv[4 + j][1] = kk2.y;
        gv[4 + j][0] = gg2.x + aa2.x;
        gv[4 + j][1] = gg2.y + aa2.y;
    }

    float out2[2];
#pragma unroll
    for (int c = 0; c < 2; c++) {
        float m = -1e30f;
#pragma unroll
        for (int j = 0; j < 8; j++) m = fmaxf(m, gv[j][c]);
        float s = 0.f;
        float acc = 0.f;
#pragma unroll
        for (int j = 0; j < 8; j++) {
            float e = __expf(gv[j][c] - m);
            s += e;
            acc += e * kvv[j][c];
        }
        out2[c] = acc / s;
    }

    float* vp = g_v + ((size_t)b * NW_ + w) * HD_ + d0;
    vp[0] = out2[0];
    vp[1] = out2[1];

    float y0 = out2[0];
    float y1 = out2[1];
    if (p >= 32) {
        int i = p - 32;
        float inv = (float)pow(10000.0, -(double)i / 32.0);
        float ang = (float)(w * RATIO_) * inv;
        float sn, cs;
        sincosf(ang, &sn, &cs);
        y0 = out2[0] * cs - out2[1] * sn;
        y1 = out2[0] * sn + out2[1] * cs;
    }
    float* kp = g_krot + ((size_t)b * NW_ + w) * HD_ + d0;
    kp[0] = y0;
    kp[1] = y1;
}

// ---------------- Q RoPE + transpose, pre-scaled ----------------
__global__ void rope_q_kernel()
{
    int idx = blockIdx.x * blockDim.x + threadIdx.x;
    if (idx >= MS_ * NH_ * 64) return;
    int p = idx & 63;
    int h = (idx >> 6) % NH_;
    int bs = idx / (64 * NH_);
    int b = bs / S_;
    int s = bs % S_;

    const float2 xv = *(const float2*)(g_q_lin + (size_t)bs * QN_ + h * HD_ + 2 * p);
    float y0 = xv.x;
    float y1 = xv.y;
    if (p >= 32) {
        int i = p - 32;
        float inv = (float)pow(10000.0, -(double)i / 32.0);
        float ang = (float)s * inv;
        float sn, cs;
        sincosf(ang, &sn, &cs);
        y0 = xv.x * cs - xv.y * sn;
        y1 = xv.x * sn + xv.y * cs;
    }
    const float scale = 0.08838834764831845f;
    float* dst = g_q_rot + (((size_t)b * NH_ + h) * S_ + s) * HD_ + 2 * p;
    dst[0] = y0 * scale;
    dst[1] = y1 * scale;
}

// ---------------- flash attention with sink (fp32 math, fp16 out) ----------------
__global__ __launch_bounds__(256) void attn_kernel(const float* __restrict__ sinks)
{
    extern __shared__ float sm[];
    float* Qs = sm;
    float* Ks = Qs + BQ * QSTR;
    float* Vs = Ks + BQ * QSTR;
    float* Ss = Vs + BQ * QSTR;
    float* rowm = Ss + BQ * SSTR;
    float* rowl = rowm + BQ;
    float* rowsc = rowl + BQ;

    int tid = threadIdx.x;
    int b = blockIdx.z;
    int h = blockIdx.y;
    int q0 = blockIdx.x * BQ;
    int ty = tid >> 4;
    int tx = tid & 15;

    const float* qsrc = g_q_rot + (((size_t)b * NH_ + h) * S_ + q0) * HD_;
#pragma unroll
    for (int t = 0; t < 8; t++) {
        int lin = tid + t * 256;
        int row = lin >> 5;
        int c4 = (lin & 31) * 4;
        *(float4*)&Qs[row * QSTR + c4] = *(const float4*)&qsrc[(size_t)row * HD_ + c4];
    }
    if (tid < BQ) {
        rowm[tid] = -1e30f;
        rowl[tid] = 0.f;
    }

    float o[4][8];
#pragma unroll
    for (int i = 0; i < 4; i++)
#pragma unroll
        for (int c = 0; c < 8; c++)
            o[i][c] = 0.f;

    int kmax = (q0 + BQ - 4) >> 2;
    if (kmax > NW_ - 1) kmax = NW_ - 1;
    int nkt = kmax / BKT + 1;

    const float* kb = g_krot + (size_t)b * NW_ * HD_;
    const float* vb = g_v + (size_t)b * NW_ * HD_;

    for (int kt = 0; kt < nkt; kt++) {
        __syncthreads();
#pragma unroll
        for (int t = 0; t < 8; t++) {
            int lin = tid + t * 256;
            int row = lin >> 5;
            int c4 = (lin & 31) * 4;
            *(float4*)&Ks[row * QSTR + c4] = *(const float4*)&kb[(size_t)(kt * BKT + row) * HD_ + c4];
            *(float4*)&Vs[row * QSTR + c4] = *(const float4*)&vb[(size_t)(kt * BKT + row) * HD_ + c4];
        }
        __syncthreads();

        float acc[4][4];
#pragma unroll
        for (int i = 0; i < 4; i++)
#pragma unroll
            for (int j = 0; j < 4; j++)
                acc[i][j] = 0.f;

        for (int d = 0; d < HD_; d += 4) {
            float4 qa[4];
            float4 ka[4];
#pragma unroll
            for (int i = 0; i < 4; i++)
                qa[i] = *(float4*)&Qs[(ty * 4 + i) * QSTR + d];
#pragma unroll
            for (int j = 0; j < 4; j++)
                ka[j] = *(float4*)&Ks[(tx + 16 * j) * QSTR + d];
#pragma unroll
            for (int i = 0; i < 4; i++) {
#pragma unroll
                for (int j = 0; j < 4; j++) {
                    acc[i][j] += qa[i].x * ka[j].x;
                    acc[i][j] += qa[i].y * ka[j].y;
                    acc[i][j] += qa[i].z * ka[j].z;
                    acc[i][j] += qa[i].w * ka[j].w;
                }
            }
        }
#pragma unroll
        for (int i = 0; i < 4; i++) {
#pragma unroll
            for (int j = 0; j < 4; j++) {
                int qg = q0 + ty * 4 + i;
                int kg = kt * BKT + tx + 16 * j;
                float sv = (qg >= 4 * kg + 3) ? acc[i][j] : -1e30f;
                Ss[(ty * 4 + i) * SSTR + tx + 16 * j] = sv;
            }
        }
        __syncthreads();

        {
            int r = tid >> 2;
            int j = tid & 3;
            float mx = -1e30f;
            for (int k = j; k < BKT; k += 4) mx = fmaxf(mx, Ss[r * SSTR + k]);
            mx = fmaxf(mx, __shfl_xor_sync(0xffffffffu, mx, 1));
            mx = fmaxf(mx, __shfl_xor_sync(0xffffffffu, mx, 2));
            float mold = rowm[r];
            float mnew = fmaxf(mold, mx);
            float ssum = 0.f;
            for (int k = j; k < BKT; k += 4) {
                float pe = __expf(Ss[r * SSTR + k] - mnew);
                Ss[r * SSTR + k] = pe;
                ssum += pe;
            }
            ssum += __shfl_xor_sync(0xffffffffu, ssum, 1);
            ssum += __shfl_xor_sync(0xffffffffu, ssum, 2);
            if (j == 0) {
                float sc = __expf(mold - mnew);
                rowsc[r] = sc;
                rowl[r] = rowl[r] * sc + ssum;
                rowm[r] = mnew;
            }
        }
        __syncthreads();

#pragma unroll
        for (int i = 0; i < 4; i++) {
            float sc = rowsc[ty * 4 + i];
#pragma unroll
            for (int c = 0; c < 8; c++)
                o[i][c] *= sc;
        }
        for (int k = 0; k < BKT; k++) {
            float4 v0 = *(float4*)&Vs[k * QSTR + tx * 8];
            float4 v1 = *(float4*)&Vs[k * QSTR + tx * 8 + 4];
#pragma unroll
            for (int i = 0; i < 4; i++) {
                float pe = Ss[(ty * 4 + i) * SSTR + k];
                o[i][0] += pe * v0.x;
                o[i][1] += pe * v0.y;
                o[i][2] += pe * v0.z;
                o[i][3] += pe * v0.w;
                o[i][4] += pe * v1.x;
                o[i][5] += pe * v1.y;
                o[i][6] += pe * v1.z;
                o[i][7] += pe * v1.w;
            }
        }
    }
    __syncthreads();

    if (tid < BQ) {
        float sh = sinks[h];
        float mold = rowm[tid];
        float mf = fmaxf(mold, sh);
        float lf = rowl[tid] * __expf(mold - mf) + __expf(sh - mf);
        rowsc[tid] = __expf(mold - mf) / lf;
    }
    __syncthreads();

#pragma unroll
    for (int i = 0; i < 4; i++) {
        int qg = q0 + ty * 4 + i;
        float sc = rowsc[ty * 4 + i];
        __half2* d2 = (__half2*)((__half*)g_h_attn + ((size_t)b * S_ + qg) * QN_ + h * HD_ + tx * 8);
        d2[0] = __floats2half2_rn(o[i][0] * sc, o[i][1] * sc);
        d2[1] = __floats2half2_rn(o[i][2] * sc, o[i][3] * sc);
        d2[2] = __floats2half2_rn(o[i][4] * sc, o[i][5] * sc);
        d2[3] = __floats2half2_rn(o[i][6] * sc, o[i][7] * sc);
    }
}

// ---------------- launch ----------------
extern "C" void kernel_launch(void* const* d_in, const int* in_sizes, int n_in,
                              void* d_out, int out_size)
{
    const float* hidden = (const float*)d_in[0];
    const float* wq = (const float*)d_in[1];
    const float* wkv = (const float*)d_in[2];
    const float* wgate = (const float*)d_in[3];
    const float* ape = (const float*)d_in[4];
    const float* sinks = (const float*)d_in[5];
    const float* wo = (const float*)d_in[6];
    float* out = (float*)d_out;

    void* p_qlin = 0;
    void* p_kv = 0;
    void* p_gate = 0;
    void* p_hh = 0;
    void* p_hwq = 0;
    void* p_hwkv = 0;
    void* p_hwg = 0;
    void* p_hwo = 0;
    void* p_hattn = 0;
    cudaGetSymbolAddress(&p_qlin, g_q_lin);
    cudaGetSymbolAddress(&p_kv, g_kv);
    cudaGetSymbolAddress(&p_gate, g_gate);
    cudaGetSymbolAddress(&p_hh, g_h_hidden);
    cudaGetSymbolAddress(&p_hwq, g_h_wq);
    cudaGetSymbolAddress(&p_hwkv, g_h_wkv);
    cudaGetSymbolAddress(&p_hwg, g_h_wgate);
    cudaGetSymbolAddress(&p_hwo, g_h_wo);
    cudaGetSymbolAddress(&p_hattn, g_h_attn);

    int n4a = (int)((size_t)MS_ * HID_ / 4);
    f2h_kernel<<<(n4a + 255) / 256, 256>>>((const float4*)hidden, (__half2*)p_hh, n4a);
    int n4b = (int)((size_t)HID_ * QN_ / 4);
    f2h_kernel<<<(n4b + 255) / 256, 256>>>((const float4*)wq, (__half2*)p_hwq, n4b);
    int n4c = (int)((size_t)HID_ * 2 * HD_ / 4);
    f2h_kernel<<<(n4c + 255) / 256, 256>>>((const float4*)wkv, (__half2*)p_hwkv, n4c);
    f2h_kernel<<<(n4c + 255) / 256, 256>>>((const float4*)wgate, (__half2*)p_hwg, n4c);
    int n4d = (int)((size_t)QN_ * HID_ / 4);
    f2h_kernel<<<(n4d + 255) / 256, 256>>>((const float4*)wo, (__half2*)p_hwo, n4d);

    hgemm<<<dim3(2 * HD_ / GBN, MS_ / GBM), 256>>>((const __half*)p_hh, (const __half*)p_hwkv, (float*)p_kv, MS_, 2 * HD_, HID_);
    hgemm<<<dim3(2 * HD_ / GBN, MS_ / GBM), 256>>>((const __half*)p_hh, (const __half*)p_hwg, (float*)p_gate, MS_, 2 * HD_, HID_);
    hgemm<<<dim3(QN_ / GBN, MS_ / GBM), 256>>>((const __half*)p_hh, (const __half*)p_hwq, (float*)p_qlin, MS_, QN_, HID_);

    pool_kernel<<<(B_ * NW_ * 64 + 255) / 256, 256>>>(ape);
    rope_q_kernel<<<(MS_ * NH_ * 64 + 255) / 256, 256>>>();

    size_t shmem = (size_t)(3 * BQ * QSTR + BQ * SSTR + 3 * BQ) * sizeof(float);
    cudaFuncSetAttribute(attn_kernel, cudaFuncAttributeMaxDynamicSharedMemorySize, (int)shmem);
    attn_kernel<<<dim3(S_ / BQ, NH_, B_), 256, shmem>>>(sinks);

    hgemm<<<dim3(HID_ / GBN, MS_ / GBM), 256>>>((const __half*)p_hattn, (const __half*)p_hwo, out, MS_, HID_, QN_);
}

// round 4
// speedup vs baseline: 4.5684x; 2.8782x over previous
#include <cuda_runtime.h>
#include <cuda_fp16.h>
#include <math.h>

#define B_     2
#define S_     4096
#define HID_   2048
#define NH_    16
#define HD_    128
#define RATIO_ 4
#define NW_    1024
#define MS_    8192
#define QN_    2048

#define GBM 128
#define GBN 128
#define GBK 32
#define APAD 8
#define BPAD 8

#define AQ  128
#define AK  64
#define QP  136

// ---------------- scratch (static device allocations) ----------------
__device__ float g_q_lin[(size_t)MS_ * QN_];
__device__ float g_kv[(size_t)MS_ * 2 * HD_];
__device__ float g_gate[(size_t)MS_ * 2 * HD_];

__device__ unsigned short g_h_hidden[(size_t)MS_ * HID_];
__device__ unsigned short g_h_wq[(size_t)HID_ * QN_];
__device__ unsigned short g_h_wkv[(size_t)HID_ * 2 * HD_];
__device__ unsigned short g_h_wgate[(size_t)HID_ * 2 * HD_];
__device__ unsigned short g_h_wo[(size_t)QN_ * HID_];
__device__ unsigned short g_h_attn[(size_t)MS_ * QN_];
__device__ unsigned short g_h_qrot[(size_t)MS_ * QN_];   // [B][NH][S][HD] fp16, pre-scaled
__device__ unsigned short g_h_krot[(size_t)B_ * NW_ * HD_];
__device__ unsigned short g_h_v[(size_t)B_ * NW_ * HD_];

// ---------------- fp32 -> fp16 ----------------
__global__ void f2h_kernel(const float4* __restrict__ in, __half2* __restrict__ out, int n4)
{
    int i = blockIdx.x * blockDim.x + threadIdx.x;
    if (i < n4) {
        float4 v = in[i];
        out[2 * i] = __floats2half2_rn(v.x, v.y);
        out[2 * i + 1] = __floats2half2_rn(v.z, v.w);
    }
}

// ---------------- PTX helpers ----------------
__device__ __forceinline__ void cp16(void* dst, const void* src)
{
    unsigned d = (unsigned)__cvta_generic_to_shared(dst);
    asm volatile("cp.async.cg.shared.global [%0], [%1], 16;" :: "r"(d), "l"(src));
}

__device__ __forceinline__ void cp_commit()
{
    asm volatile("cp.async.commit_group;");
}

__device__ __forceinline__ void cp_wait1()
{
    asm volatile("cp.async.wait_group 1;");
}

__device__ __forceinline__ void cp_wait0()
{
    asm volatile("cp.async.wait_group 0;");
}

__device__ __forceinline__ void ldm_x4(unsigned* r, const void* p)
{
    unsigned a = (unsigned)__cvta_generic_to_shared(p);
    asm volatile("ldmatrix.sync.aligned.m8n8.x4.shared.b16 {%0,%1,%2,%3}, [%4];"
                 : "=r"(r[0]), "=r"(r[1]), "=r"(r[2]), "=r"(r[3]) : "r"(a));
}

__device__ __forceinline__ void ldm_x4_t(unsigned* r, const void* p)
{
    unsigned a = (unsigned)__cvta_generic_to_shared(p);
    asm volatile("ldmatrix.sync.aligned.m8n8.x4.trans.shared.b16 {%0,%1,%2,%3}, [%4];"
                 : "=r"(r[0]), "=r"(r[1]), "=r"(r[2]), "=r"(r[3]) : "r"(a));
}

__device__ __forceinline__ void mma16816(float* c, const unsigned* a, unsigned b0, unsigned b1)
{
    asm volatile("mma.sync.aligned.m16n8k16.row.col.f32.f16.f16.f32 "
                 "{%0,%1,%2,%3},{%4,%5,%6,%7},{%8,%9},{%0,%1,%2,%3};"
                 : "+f"(c[0]), "+f"(c[1]), "+f"(c[2]), "+f"(c[3])
                 : "r"(a[0]), "r"(a[1]), "r"(a[2]), "r"(a[3]), "r"(b0), "r"(b1));
}

// ---------------- 128x128x32 fp16 tensor-core GEMM ----------------
__global__ __launch_bounds__(256) void hgemm(
    const __half* __restrict__ A, const __half* __restrict__ Bm,
    float* __restrict__ C, int M, int N, int K)
{
    __shared__ __half As[2][GBM][GBK + APAD];
    __shared__ __half Bs[2][GBK][GBN + BPAD];

    int tid = threadIdx.x;
    int lane = tid & 31;
    int wid = tid >> 5;
    int warpM = wid & 3;
    int warpN = wid >> 2;
    int rowBase = blockIdx.y * GBM;
    int colBase = blockIdx.x * GBN;

    float acc[2][8][4];
    for (int i = 0; i < 2; i++)
        for (int j = 0; j < 8; j++)
            for (int c = 0; c < 4; c++)
                acc[i][j][c] = 0.f;

    int arow = tid >> 2;
    int acol = (tid & 3) * 8;
    int brow = tid >> 4;
    int bcol = (tid & 15) * 8;

    const __half* Ag0 = A + (size_t)(rowBase + arow) * K + acol;
    const __half* Bg0 = Bm + (size_t)brow * N + colBase + bcol;

    int T = K / GBK;

    cp16(&As[0][arow][acol], Ag0);
    cp16(&As[0][arow + 64][acol], Ag0 + (size_t)64 * K);
    cp16(&Bs[0][brow][bcol], Bg0);
    cp16(&Bs[0][brow + 16][bcol], Bg0 + (size_t)16 * N);
    cp_commit();

    for (int t = 0; t < T; t++) {
        int s = t & 1;
        if (t + 1 < T) {
            const __half* Ag = Ag0 + (size_t)(t + 1) * GBK;
            const __half* Bg = Bg0 + (size_t)(t + 1) * GBK * N;
            cp16(&As[s ^ 1][arow][acol], Ag);
            cp16(&As[s ^ 1][arow + 64][acol], Ag + (size_t)64 * K);
            cp16(&Bs[s ^ 1][brow][bcol], Bg);
            cp16(&Bs[s ^ 1][brow + 16][bcol], Bg + (size_t)16 * N);
            cp_commit();
            cp_wait1();
        } else {
            cp_wait0();
        }
        __syncthreads();

#pragma unroll
        for (int kk = 0; kk < GBK; kk += 16) {
            unsigned afr[2][4];
            unsigned bfr[4][4];
#pragma unroll
            for (int i = 0; i < 2; i++) {
                ldm_x4(afr[i], &As[s][warpM * 32 + i * 16 + (lane & 15)][kk + (lane >> 4) * 8]);
            }
#pragma unroll
            for (int j = 0; j < 4; j++) {
                ldm_x4_t(bfr[j], &Bs[s][kk + ((lane >> 3) & 1) * 8 + (lane & 7)][warpN * 64 + j * 16 + (lane >> 4) * 8]);
            }
#pragma unroll
            for (int i = 0; i < 2; i++) {
#pragma unroll
                for (int j = 0; j < 4; j++) {
                    mma16816(acc[i][2 * j], afr[i], bfr[j][0], bfr[j][1]);
                    mma16816(acc[i][2 * j + 1], afr[i], bfr[j][2], bfr[j][3]);
                }
            }
        }
        __syncthreads();
    }

    int r0 = rowBase + warpM * 32 + (lane >> 2);
    int c0 = colBase + warpN * 64 + (lane & 3) * 2;
#pragma unroll
    for (int i = 0; i < 2; i++) {
#pragma unroll
        for (int j = 0; j < 8; j++) {
            float2* p0 = (float2*)&C[(size_t)(r0 + i * 16) * N + c0 + j * 8];
            p0[0] = make_float2(acc[i][j][0], acc[i][j][1]);
            float2* p1 = (float2*)&C[(size_t)(r0 + i * 16 + 8) * N + c0 + j * 8];
            p1[0] = make_float2(acc[i][j][2], acc[i][j][3]);
        }
    }
}

// ---------------- overlap-pool + K-RoPE (fp16 outputs) ----------------
__global__ void pool_kernel(const float* __restrict__ ape)
{
    int idx = blockIdx.x * blockDim.x + threadIdx.x;
    if (idx >= B_ * NW_ * 64) return;
    int p = idx & 63;
    int w = (idx >> 6) % NW_;
    int b = idx / (64 * NW_);
    int d0 = 2 * p;

    const float* kvb = g_kv + (size_t)b * S_ * 2 * HD_;
    const float* gb = g_gate + (size_t)b * S_ * 2 * HD_;

    float kvv[8][2];
    float gv[8][2];
#pragma unroll
    for (int j = 0; j < RATIO_; j++) {
        if (w > 0) {
            int t = (w - 1) * RATIO_ + j;
            float2 kk = *(const float2*)&kvb[(size_t)t * 2 * HD_ + d0];
            float2 gg = *(const float2*)&gb[(size_t)t * 2 * HD_ + d0];
            float2 aa = *(const float2*)&ape[(size_t)j * 2 * HD_ + d0];
            kvv[j][0] = kk.x;
            kvv[j][1] = kk.y;
            gv[j][0] = gg.x + aa.x;
            gv[j][1] = gg.y + aa.y;
        } else {
            kvv[j][0] = 0.f;
            kvv[j][1] = 0.f;
            gv[j][0] = -1e30f;
            gv[j][1] = -1e30f;
        }
        int t2 = w * RATIO_ + j;
        float2 kk2 = *(const float2*)&kvb[(size_t)t2 * 2 * HD_ + HD_ + d0];
        float2 gg2 = *(const float2*)&gb[(size_t)t2 * 2 * HD_ + HD_ + d0];
        float2 aa2 = *(const float2*)&ape[(size_t)j * 2 * HD_ + HD_ + d0];
        kvv[4 + j][0] = kk2.x;
        kvv[4 + j][1] = kk2.y;
        gv[4 + j][0] = gg2.x + aa2.x;
        gv[4 + j][1] = gg2.y + aa2.y;
    }

    float out2[2];
#pragma unroll
    for (int c = 0; c < 2; c++) {
        float m = -1e30f;
#pragma unroll
        for (int j = 0; j < 8; j++) m = fmaxf(m, gv[j][c]);
        float s = 0.f;
        float acc = 0.f;
#pragma unroll
        for (int j = 0; j < 8; j++) {
            float e = __expf(gv[j][c] - m);
            s += e;
            acc += e * kvv[j][c];
        }
        out2[c] = acc / s;
    }

    __half2* vp = (__half2*)((__half*)g_h_v + ((size_t)b * NW_ + w) * HD_ + d0);
    vp[0] = __floats2half2_rn(out2[0], out2[1]);

    float y0 = out2[0];
    float y1 = out2[1];
    if (p >= 32) {
        int i = p - 32;
        float inv = (float)pow(10000.0, -(double)i / 32.0);
        float ang = (float)(w * RATIO_) * inv;
        float sn, cs;
        sincosf(ang, &sn, &cs);
        y0 = out2[0] * cs - out2[1] * sn;
        y1 = out2[0] * sn + out2[1] * cs;
    }
    __half2* kp = (__half2*)((__half*)g_h_krot + ((size_t)b * NW_ + w) * HD_ + d0);
    kp[0] = __floats2half2_rn(y0, y1);
}

// ---------------- Q RoPE + transpose, pre-scaled, fp16 out ----------------
__global__ void rope_q_kernel()
{
    int idx = blockIdx.x * blockDim.x + threadIdx.x;
    if (idx >= MS_ * NH_ * 64) return;
    int p = idx & 63;
    int h = (idx >> 6) % NH_;
    int bs = idx / (64 * NH_);
    int b = bs / S_;
    int s = bs % S_;

    const float2 xv = *(const float2*)(g_q_lin + (size_t)bs * QN_ + h * HD_ + 2 * p);
    float y0 = xv.x;
    float y1 = xv.y;
    if (p >= 32) {
        int i = p - 32;
        float inv = (float)pow(10000.0, -(double)i / 32.0);
        float ang = (float)s * inv;
        float sn, cs;
        sincosf(ang, &sn, &cs);
        y0 = xv.x * cs - xv.y * sn;
        y1 = xv.x * sn + xv.y * cs;
    }
    const float scale = 0.08838834764831845f;
    __half2* dst = (__half2*)((__half*)g_h_qrot + (((size_t)b * NH_ + h) * S_ + s) * HD_ + 2 * p);
    dst[0] = __floats2half2_rn(y0 * scale, y1 * scale);
}

// ---------------- tensor-core flash attention with sink ----------------
__global__ __launch_bounds__(256, 1) void attn_mma_kernel(const float* __restrict__ sinks)
{
    extern __shared__ __half smh[];
    __half* Qs = smh;                       // [AQ][QP]
    __half* Ks = Qs + AQ * QP;              // [AK][QP]
    __half* Vs = Ks + AK * QP;              // [AK][QP]

    int tid = threadIdx.x;
    int lane = tid & 31;
    int wid = tid >> 5;                     // 0..7, 16 q-rows each
    int b = blockIdx.z;
    int h = blockIdx.y;
    int q0 = blockIdx.x * AQ;

    // load Q tile (128 rows x 128 halves)
    const __half* qsrc = (const __half*)g_h_qrot + (((size_t)b * NH_ + h) * S_ + q0) * HD_;
#pragma unroll
    for (int t = 0; t < 8; t++) {
        int lin = tid + t * 256;
        int row = lin >> 4;
        int c8 = (lin & 15) * 8;
        *(uint4*)&Qs[row * QP + c8] = *(const uint4*)&qsrc[(size_t)row * HD_ + c8];
    }

    float m0 = -1e30f, m1 = -1e30f;
    float l0 = 0.f, l1 = 0.f;
    float oacc[16][4];
#pragma unroll
    for (int j = 0; j < 16; j++)
#pragma unroll
        for (int c = 0; c < 4; c++)
            oacc[j][c] = 0.f;

    int kmax = (q0 + AQ - 4) >> 2;
    if (kmax > NW_ - 1) kmax = NW_ - 1;
    int nkt = kmax / AK + 1;

    const __half* kb = (const __half*)g_h_krot + (size_t)b * NW_ * HD_;
    const __half* vb = (const __half*)g_h_v + (size_t)b * NW_ * HD_;

    int row0 = q0 + wid * 16 + (lane >> 2);
    int row1 = row0 + 8;

    for (int kt = 0; kt < nkt; kt++) {
        __syncthreads();
#pragma unroll
        for (int t = 0; t < 4; t++) {
            int lin = tid + t * 256;
            int row = lin >> 4;
            int c8 = (lin & 15) * 8;
            *(uint4*)&Ks[row * QP + c8] = *(const uint4*)&kb[(size_t)(kt * AK + row) * HD_ + c8];
            *(uint4*)&Vs[row * QP + c8] = *(const uint4*)&vb[(size_t)(kt * AK + row) * HD_ + c8];
        }
        __syncthreads();

        // ---- S = Q K^T : 8 n8-tiles over 64 keys ----
        float sacc[8][4];
#pragma unroll
        for (int j = 0; j < 8; j++)
#pragma unroll
            for (int c = 0; c < 4; c++)
                sacc[j][c] = 0.f;

#pragma unroll
        for (int kk = 0; kk < HD_; kk += 16) {
            unsigned afr[4];
            ldm_x4(afr, &Qs[(wid * 16 + (lane & 15)) * QP + kk + (lane >> 4) * 8]);
#pragma unroll
            for (int j = 0; j < 4; j++) {
                unsigned bfr[4];
                ldm_x4(bfr, &Ks[(j * 16 + (lane >> 4) * 8 + (lane & 7)) * QP + kk + ((lane >> 3) & 1) * 8]);
                mma16816(sacc[2 * j], afr, bfr[0], bfr[1]);
                mma16816(sacc[2 * j + 1], afr, bfr[2], bfr[3]);
            }
        }

        // ---- mask ----
#pragma unroll
        for (int j = 0; j < 8; j++) {
            int kg = kt * AK + j * 8 + (lane & 3) * 2;
            if (row0 < 4 * kg + 3) sacc[j][0] = -1e30f;
            if (row0 < 4 * kg + 7) sacc[j][1] = -1e30f;
            if (row1 < 4 * kg + 3) sacc[j][2] = -1e30f;
            if (row1 < 4 * kg + 7) sacc[j][3] = -1e30f;
        }

        // ---- online softmax ----
        float mx0 = -1e30f, mx1 = -1e30f;
#pragma unroll
        for (int j = 0; j < 8; j++) {
            mx0 = fmaxf(mx0, fmaxf(sacc[j][0], sacc[j][1]));
            mx1 = fmaxf(mx1, fmaxf(sacc[j][2], sacc[j][3]));
        }
        mx0 = fmaxf(mx0, __shfl_xor_sync(0xffffffffu, mx0, 1));
        mx0 = fmaxf(mx0, __shfl_xor_sync(0xffffffffu, mx0, 2));
        mx1 = fmaxf(mx1, __shfl_xor_sync(0xffffffffu, mx1, 1));
        mx1 = fmaxf(mx1, __shfl_xor_sync(0xffffffffu, mx1, 2));

        float mn0 = fmaxf(m0, mx0);
        float mn1 = fmaxf(m1, mx1);
        float sc0 = __expf(m0 - mn0);
        float sc1 = __expf(m1 - mn1);
        m0 = mn0;
        m1 = mn1;

        unsigned ph[8][2];
        float rs0 = 0.f, rs1 = 0.f;
#pragma unroll
        for (int j = 0; j < 8; j++) {
            float p00 = __expf(sacc[j][0] - m0);
            float p01 = __expf(sacc[j][1] - m0);
            float p10 = __expf(sacc[j][2] - m1);
            float p11 = __expf(sacc[j][3] - m1);
            rs0 += p00 + p01;
            rs1 += p10 + p11;
            __half2 h0 = __floats2half2_rn(p00, p01);
            __half2 h1 = __floats2half2_rn(p10, p11);
            ph[j][0] = *reinterpret_cast<unsigned*>(&h0);
            ph[j][1] = *reinterpret_cast<unsigned*>(&h1);
        }
        rs0 += __shfl_xor_sync(0xffffffffu, rs0, 1);
        rs0 += __shfl_xor_sync(0xffffffffu, rs0, 2);
        rs1 += __shfl_xor_sync(0xffffffffu, rs1, 1);
        rs1 += __shfl_xor_sync(0xffffffffu, rs1, 2);
        l0 = l0 * sc0 + rs0;
        l1 = l1 * sc1 + rs1;

#pragma unroll
        for (int j = 0; j < 16; j++) {
            oacc[j][0] *= sc0;
            oacc[j][1] *= sc0;
            oacc[j][2] *= sc1;
            oacc[j][3] *= sc1;
        }

        // ---- O += P V : 4 k16-chunks over 64 keys, 16 n8-tiles over 128 dims ----
#pragma unroll
        for (int c = 0; c < 4; c++) {
            unsigned pa[4];
            pa[0] = ph[2 * c][0];
            pa[1] = ph[2 * c][1];
            pa[2] = ph[2 * c + 1][0];
            pa[3] = ph[2 * c + 1][1];
#pragma unroll
            for (int j = 0; j < 8; j++) {
                unsigned bfr[4];
                ldm_x4_t(bfr, &Vs[(c * 16 + ((lane >> 3) & 1) * 8 + (lane & 7)) * QP + j * 16 + (lane >> 4) * 8]);
                mma16816(oacc[2 * j], pa, bfr[0], bfr[1]);
                mma16816(oacc[2 * j + 1], pa, bfr[2], bfr[3]);
            }
        }
    }

    // ---- finalize with sink ----
    float sh = sinks[h];
    float mf0 = fmaxf(m0, sh);
    float mf1 = fmaxf(m1, sh);
    float lf0 = l0 * __expf(m0 - mf0) + __expf(sh - mf0);
    float lf1 = l1 * __expf(m1 - mf1) + __expf(sh - mf1);
    float fs0 = __expf(m0 - mf0) / lf0;
    float fs1 = __expf(m1 - mf1) / lf1;

    __half* ob = (__half*)g_h_attn;
    size_t base0 = ((size_t)b * S_ + row0) * QN_ + h * HD_ + (lane & 3) * 2;
    size_t base1 = ((size_t)b * S_ + row1) * QN_ + h * HD_ + (lane & 3) * 2;
#pragma unroll
    for (int j = 0; j < 16; j++) {
        __half2 w0 = __floats2half2_rn(oacc[j][0] * fs0, oacc[j][1] * fs0);
        __half2 w1 = __floats2half2_rn(oacc[j][2] * fs1, oacc[j][3] * fs1);
        *(__half2*)&ob[base0 + j * 8] = w0;
        *(__half2*)&ob[base1 + j * 8] = w1;
    }
}

// ---------------- launch ----------------
extern "C" void kernel_launch(void* const* d_in, const int* in_sizes, int n_in,
                              void* d_out, int out_size)
{
    const float* hidden = (const float*)d_in[0];
    const float* wq = (const float*)d_in[1];
    const float* wkv = (const float*)d_in[2];
    const float* wgate = (const float*)d_in[3];
    const float* ape = (const float*)d_in[4];
    const float* sinks = (const float*)d_in[5];
    const float* wo = (const float*)d_in[6];
    float* out = (float*)d_out;

    void* p_qlin = 0;
    void* p_kv = 0;
    void* p_gate = 0;
    void* p_hh = 0;
    void* p_hwq = 0;
    void* p_hwkv = 0;
    void* p_hwg = 0;
    void* p_hwo = 0;
    void* p_hattn = 0;
    cudaGetSymbolAddress(&p_qlin, g_q_lin);
    cudaGetSymbolAddress(&p_kv, g_kv);
    cudaGetSymbolAddress(&p_gate, g_gate);
    cudaGetSymbolAddress(&p_hh, g_h_hidden);
    cudaGetSymbolAddress(&p_hwq, g_h_wq);
    cudaGetSymbolAddress(&p_hwkv, g_h_wkv);
    cudaGetSymbolAddress(&p_hwg, g_h_wgate);
    cudaGetSymbolAddress(&p_hwo, g_h_wo);
    cudaGetSymbolAddress(&p_hattn, g_h_attn);

    int n4a = (int)((size_t)MS_ * HID_ / 4);
    f2h_kernel<<<(n4a + 255) / 256, 256>>>((const float4*)hidden, (__half2*)p_hh, n4a);
    int n4b = (int)((size_t)HID_ * QN_ / 4);
    f2h_kernel<<<(n4b + 255) / 256, 256>>>((const float4*)wq, (__half2*)p_hwq, n4b);
    int n4c = (int)((size_t)HID_ * 2 * HD_ / 4);
    f2h_kernel<<<(n4c + 255) / 256, 256>>>((const float4*)wkv, (__half2*)p_hwkv, n4c);
    f2h_kernel<<<(n4c + 255) / 256, 256>>>((const float4*)wgate, (__half2*)p_hwg, n4c);
    int n4d = (int)((size_t)QN_ * HID_ / 4);
    f2h_kernel<<<(n4d + 255) / 256, 256>>>((const float4*)wo, (__half2*)p_hwo, n4d);

    hgemm<<<dim3(2 * HD_ / GBN, MS_ / GBM), 256>>>((const __half*)p_hh, (const __half*)p_hwkv, (float*)p_kv, MS_, 2 * HD_, HID_);
    hgemm<<<dim3(2 * HD_ / GBN, MS_ / GBM), 256>>>((const __half*)p_hh, (const __half*)p_hwg, (float*)p_gate, MS_, 2 * HD_, HID_);
    hgemm<<<dim3(QN_ / GBN, MS_ / GBM), 256>>>((const __half*)p_hh, (const __half*)p_hwq, (float*)p_qlin, MS_, QN_, HID_);

    pool_kernel<<<(B_ * NW_ * 64 + 255) / 256, 256>>>(ape);
    rope_q_kernel<<<(MS_ * NH_ * 64 + 255) / 256, 256>>>();

    size_t shmem = (size_t)(AQ + 2 * AK) * QP * sizeof(__half);
    cudaFuncSetAttribute(attn_mma_kernel, cudaFuncAttributeMaxDynamicSharedMemorySize, (int)shmem);
    attn_mma_kernel<<<dim3(S_ / AQ, NH_, B_), 256, shmem>>>(sinks);

    hgemm<<<dim3(HID_ / GBN, MS_ / GBM), 256>>>((const __half*)p_hattn, (const __half*)p_hwo, out, MS_, HID_, QN_);
}

// round 6
// speedup vs baseline: 4.6761x; 1.0236x over previous
#include <cuda_runtime.h>
#include <cuda_fp16.h>
#include <math.h>

#define B_     2
#define S_     4096
#define HID_   2048
#define NH_    16
#define HD_    128
#define RATIO_ 4
#define NW_    1024
#define MS_    8192
#define QN_    2048
#define QKVN   2560   /* fused q(2048) | kv(256) | gate(256) */

#define AQ  128
#define AK  64
#define QP  136

#define GBM 128
#define GBN 128
#define GBK 32
#define ASTR 40      /* 32 + 8 pad, halfs */
#define BSTR 136     /* 128 + 8 pad, halfs */
#define ASTAGE (GBM * ASTR)   /* 5120 halfs */
#define BSTAGE (GBK * BSTR)   /* 4352 halfs */
#define NSTAGE 3
#define HG_SMEM ((NSTAGE * (ASTAGE + BSTAGE)) * 2)  /* 56832 bytes */

// ---------------- scratch (static device allocations) ----------------
__device__ float g_qkvg[(size_t)MS_ * QKVN];

__device__ unsigned short g_h_hidden[(size_t)MS_ * HID_];
__device__ unsigned short g_h_wfused[(size_t)HID_ * QKVN];
__device__ unsigned short g_h_wo[(size_t)QN_ * HID_];
__device__ unsigned short g_h_attn[(size_t)MS_ * QN_];
__device__ unsigned short g_h_qrot[(size_t)MS_ * QN_];
__device__ unsigned short g_h_krot[(size_t)B_ * NW_ * HD_];
__device__ unsigned short g_h_v[(size_t)B_ * NW_ * HD_];

// ---------------- fp32 -> fp16 (plain) ----------------
__global__ void f2h_kernel(const float4* __restrict__ in, __half2* __restrict__ out, int n4)
{
    int i = blockIdx.x * blockDim.x + threadIdx.x;
    if (i < n4) {
        float4 v = in[i];
        out[2 * i] = __floats2half2_rn(v.x, v.y);
        out[2 * i + 1] = __floats2half2_rn(v.z, v.w);
    }
}

// ---------------- pack wq|wkv|wgate -> fp16 [HID][QKVN] ----------------
__global__ void pack_w_kernel(const float* __restrict__ wq, const float* __restrict__ wkv,
                              const float* __restrict__ wgate, __half* __restrict__ dst)
{
    int idx = blockIdx.x * blockDim.x + threadIdx.x;
    if (idx >= HID_ * QKVN) return;
    int k = idx / QKVN;
    int n = idx % QKVN;
    float v;
    if (n < QN_) {
        v = wq[(size_t)k * QN_ + n];
    } else if (n < QN_ + 256) {
        v = wkv[(size_t)k * 256 + (n - QN_)];
    } else {
        v = wgate[(size_t)k * 256 + (n - QN_ - 256)];
    }
    dst[idx] = __float2half(v);
}

// ---------------- PTX helpers ----------------
__device__ __forceinline__ unsigned su32(const void* p)
{
    return (unsigned)__cvta_generic_to_shared(p);
}

__device__ __forceinline__ void cp16(void* dst, const void* src)
{
    unsigned d = su32(dst);
    asm volatile("cp.async.cg.shared.global [%0], [%1], 16;" :: "r"(d), "l"(src));
}

__device__ __forceinline__ void cp_commit()
{
    asm volatile("cp.async.commit_group;");
}

__device__ __forceinline__ void cp_wait1()
{
    asm volatile("cp.async.wait_group 1;");
}

__device__ __forceinline__ void cp_wait0()
{
    asm volatile("cp.async.wait_group 0;");
}

__device__ __forceinline__ void ldm_x4(unsigned* r, const void* p)
{
    unsigned a = su32(p);
    asm volatile("ldmatrix.sync.aligned.m8n8.x4.shared.b16 {%0,%1,%2,%3}, [%4];"
                 : "=r"(r[0]), "=r"(r[1]), "=r"(r[2]), "=r"(r[3]) : "r"(a));
}

__device__ __forceinline__ void ldm_x4_t(unsigned* r, const void* p)
{
    unsigned a = su32(p);
    asm volatile("ldmatrix.sync.aligned.m8n8.x4.trans.shared.b16 {%0,%1,%2,%3}, [%4];"
                 : "=r"(r[0]), "=r"(r[1]), "=r"(r[2]), "=r"(r[3]) : "r"(a));
}

__device__ __forceinline__ void mma16816(float* c, const unsigned* a, unsigned b0, unsigned b1)
{
    asm volatile("mma.sync.aligned.m16n8k16.row.col.f32.f16.f16.f32 "
                 "{%0,%1,%2,%3},{%4,%5,%6,%7},{%8,%9},{%0,%1,%2,%3};"
                 : "+f"(c[0]), "+f"(c[1]), "+f"(c[2]), "+f"(c[3])
                 : "r"(a[0]), "r"(a[1]), "r"(a[2]), "r"(a[3]), "r"(b0), "r"(b1));
}

// ---------------- 128x128x32, 3-stage pipelined fp16 HGEMM ----------------
__global__ __launch_bounds__(256, 2) void hgemm(
    const __half* __restrict__ A, const __half* __restrict__ Bm,
    float* __restrict__ C, int M, int N, int K)
{
    extern __shared__ __half hsm[];
    __half* As = hsm;                          // [NSTAGE][GBM][ASTR]
    __half* Bs = hsm + NSTAGE * ASTAGE;        // [NSTAGE][GBK][BSTR]

    int tid = threadIdx.x;
    int lane = tid & 31;
    int wid = tid >> 5;
    int warpM = wid & 3;
    int warpN = wid >> 2;
    int rowBase = blockIdx.y * GBM;
    int colBase = blockIdx.x * GBN;

    float acc[2][8][4];
#pragma unroll
    for (int i = 0; i < 2; i++)
#pragma unroll
        for (int j = 0; j < 8; j++)
#pragma unroll
            for (int c = 0; c < 4; c++)
                acc[i][j][c] = 0.f;

    int arow = tid >> 2;
    int acol = (tid & 3) * 8;
    int brow = tid >> 4;
    int bcol = (tid & 15) * 8;

    const __half* Ag0 = A + (size_t)(rowBase + arow) * K + acol;
    const __half* Bg0 = Bm + (size_t)brow * N + colBase + bcol;

    int T = K / GBK;

    // prologue: stages 0, 1
#pragma unroll
    for (int s = 0; s < 2; s++) {
        const __half* Ag = Ag0 + (size_t)s * GBK;
        const __half* Bg = Bg0 + (size_t)s * GBK * N;
        cp16(&As[s * ASTAGE + arow * ASTR + acol], Ag);
        cp16(&As[s * ASTAGE + (arow + 64) * ASTR + acol], Ag + (size_t)64 * K);
        cp16(&Bs[s * BSTAGE + brow * BSTR + bcol], Bg);
        cp16(&Bs[s * BSTAGE + (brow + 16) * BSTR + bcol], Bg + (size_t)16 * N);
        cp_commit();
    }

    for (int t = 0; t < T; t++) {
        if (t < T - 1) {
            cp_wait1();
        } else {
            cp_wait0();
        }
        __syncthreads();

        if (t + 2 < T) {
            int so = (t + 2) % NSTAGE;
            const __half* Ag = Ag0 + (size_t)(t + 2) * GBK;
            const __half* Bg = Bg0 + (size_t)(t + 2) * GBK * N;
            cp16(&As[so * ASTAGE + arow * ASTR + acol], Ag);
            cp16(&As[so * ASTAGE + (arow + 64) * ASTR + acol], Ag + (size_t)64 * K);
            cp16(&Bs[so * BSTAGE + brow * BSTR + bcol], Bg);
            cp16(&Bs[so * BSTAGE + (brow + 16) * BSTR + bcol], Bg + (size_t)16 * N);
            cp_commit();
        }

        int s = t % NSTAGE;
        const __half* Asb = &As[s * ASTAGE];
        const __half* Bsb = &Bs[s * BSTAGE];
#pragma unroll
        for (int kk = 0; kk < GBK; kk += 16) {
            unsigned afr[2][4];
            unsigned bfr[4][4];
#pragma unroll
            for (int i = 0; i < 2; i++) {
                ldm_x4(afr[i], &Asb[(warpM * 32 + i * 16 + (lane & 15)) * ASTR + kk + (lane >> 4) * 8]);
            }
#pragma unroll
            for (int j = 0; j < 4; j++) {
                ldm_x4_t(bfr[j], &Bsb[(kk + ((lane >> 3) & 1) * 8 + (lane & 7)) * BSTR + warpN * 64 + j * 16 + (lane >> 4) * 8]);
            }
#pragma unroll
            for (int i = 0; i < 2; i++) {
#pragma unroll
                for (int j = 0; j < 4; j++) {
                    mma16816(acc[i][2 * j], afr[i], bfr[j][0], bfr[j][1]);
                    mma16816(acc[i][2 * j + 1], afr[i], bfr[j][2], bfr[j][3]);
                }
            }
        }
    }

    int r0 = rowBase + warpM * 32 + (lane >> 2);
    int c0 = colBase + warpN * 64 + (lane & 3) * 2;
#pragma unroll
    for (int i = 0; i < 2; i++) {
#pragma unroll
        for (int j = 0; j < 8; j++) {
            float2* p0 = (float2*)&C[(size_t)(r0 + i * 16) * N + c0 + j * 8];
            p0[0] = make_float2(acc[i][j][0], acc[i][j][1]);
            float2* p1 = (float2*)&C[(size_t)(r0 + i * 16 + 8) * N + c0 + j * 8];
            p1[0] = make_float2(acc[i][j][2], acc[i][j][3]);
        }
    }
}

// ---------------- overlap-pool + K-RoPE (reads fused qkvg buffer) ----------------
__global__ void pool_kernel(const float* __restrict__ ape)
{
    int idx = blockIdx.x * blockDim.x + threadIdx.x;
    if (idx >= B_ * NW_ * 64) return;
    int p = idx & 63;
    int w = (idx >> 6) % NW_;
    int b = idx / (64 * NW_);
    int d0 = 2 * p;

    const float* base = g_qkvg + (size_t)b * S_ * QKVN;

    float kvv[8][2];
    float gv[8][2];
#pragma unroll
    for (int j = 0; j < RATIO_; j++) {
        if (w > 0) {
            int t = (w - 1) * RATIO_ + j;
            const float* rowp = base + (size_t)t * QKVN;
            float2 kk = *(const float2*)&rowp[QN_ + d0];
            float2 gg = *(const float2*)&rowp[QN_ + 256 + d0];
            float2 aa = *(const float2*)&ape[(size_t)j * 2 * HD_ + d0];
            kvv[j][0] = kk.x;
            kvv[j][1] = kk.y;
            gv[j][0] = gg.x + aa.x;
            gv[j][1] = gg.y + aa.y;
        } else {
            kvv[j][0] = 0.f;
            kvv[j][1] = 0.f;
            gv[j][0] = -1e30f;
            gv[j][1] = -1e30f;
        }
        int t2 = w * RATIO_ + j;
        const float* rowp2 = base + (size_t)t2 * QKVN;
        float2 kk2 = *(const float2*)&rowp2[QN_ + HD_ + d0];
        float2 gg2 = *(const float2*)&rowp2[QN_ + 256 + HD_ + d0];
        float2 aa2 = *(const float2*)&ape[(size_t)j * 2 * HD_ + HD_ + d0];
        kvv[4 + j][0] = kk2.x;
        kvv[4 + j][1] = kk2.y;
        gv[4 + j][0] = gg2.x + aa2.x;
        gv[4 + j][1] = gg2.y + aa2.y;
    }

    float out2[2];
#pragma unroll
    for (int c = 0; c < 2; c++) {
        float m = -1e30f;
#pragma unroll
        for (int j = 0; j < 8; j++) m = fmaxf(m, gv[j][c]);
        float s = 0.f;
        float acc = 0.f;
#pragma unroll
        for (int j = 0; j < 8; j++) {
            float e = __expf(gv[j][c] - m);
            s += e;
            acc += e * kvv[j][c];
        }
        out2[c] = acc / s;
    }

    __half2* vp = (__half2*)((__half*)g_h_v + ((size_t)b * NW_ + w) * HD_ + d0);
    vp[0] = __floats2half2_rn(out2[0], out2[1]);

    float y0 = out2[0];
    float y1 = out2[1];
    if (p >= 32) {
        int i = p - 32;
        float inv = (float)pow(10000.0, -(double)i / 32.0);
        float ang = (float)(w * RATIO_) * inv;
        float sn, cs;
        sincosf(ang, &sn, &cs);
        y0 = out2[0] * cs - out2[1] * sn;
        y1 = out2[0] * sn + out2[1] * cs;
    }
    __half2* kp = (__half2*)((__half*)g_h_krot + ((size_t)b * NW_ + w) * HD_ + d0);
    kp[0] = __floats2half2_rn(y0, y1);
}

// ---------------- Q RoPE + transpose, pre-scaled, fp16 out ----------------
__global__ void rope_q_kernel()
{
    int idx = blockIdx.x * blockDim.x + threadIdx.x;
    if (idx >= MS_ * NH_ * 64) return;
    int p = idx & 63;
    int h = (idx >> 6) % NH_;
    int bs = idx / (64 * NH_);
    int b = bs / S_;
    int s = bs % S_;

    const float2 xv = *(const float2*)(g_qkvg + (size_t)bs * QKVN + h * HD_ + 2 * p);
    float y0 = xv.x;
    float y1 = xv.y;
    if (p >= 32) {
        int i = p - 32;
        float inv = (float)pow(10000.0, -(double)i / 32.0);
        float ang = (float)s * inv;
        float sn, cs;
        sincosf(ang, &sn, &cs);
        y0 = xv.x * cs - xv.y * sn;
        y1 = xv.x * sn + xv.y * cs;
    }
    const float scale = 0.08838834764831845f;
    __half2* dst = (__half2*)((__half*)g_h_qrot + (((size_t)b * NH_ + h) * S_ + s) * HD_ + 2 * p);
    dst[0] = __floats2half2_rn(y0 * scale, y1 * scale);
}

// ---------------- tensor-core flash attention with sink ----------------
__global__ __launch_bounds__(256, 1) void attn_mma_kernel(const float* __restrict__ sinks)
{
    extern __shared__ __half smh[];
    __half* Qs = smh;
    __half* Ks = Qs + AQ * QP;
    __half* Vs = Ks + AK * QP;

    int tid = threadIdx.x;
    int lane = tid & 31;
    int wid = tid >> 5;
    int b = blockIdx.z;
    int h = blockIdx.y;
    int q0 = blockIdx.x * AQ;

    const __half* qsrc = (const __half*)g_h_qrot + (((size_t)b * NH_ + h) * S_ + q0) * HD_;
#pragma unroll
    for (int t = 0; t < 8; t++) {
        int lin = tid + t * 256;
        int row = lin >> 4;
        int c8 = (lin & 15) * 8;
        *(uint4*)&Qs[row * QP + c8] = *(const uint4*)&qsrc[(size_t)row * HD_ + c8];
    }

    float m0 = -1e30f, m1 = -1e30f;
    float l0 = 0.f, l1 = 0.f;
    float oacc[16][4];
#pragma unroll
    for (int j = 0; j < 16; j++)
#pragma unroll
        for (int c = 0; c < 4; c++)
            oacc[j][c] = 0.f;

    int kmax = (q0 + AQ - 4) >> 2;
    if (kmax > NW_ - 1) kmax = NW_ - 1;
    int nkt = kmax / AK + 1;

    const __half* kb = (const __half*)g_h_krot + (size_t)b * NW_ * HD_;
    const __half* vb = (const __half*)g_h_v + (size_t)b * NW_ * HD_;

    int row0 = q0 + wid * 16 + (lane >> 2);
    int row1 = row0 + 8;

    for (int kt = 0; kt < nkt; kt++) {
        __syncthreads();
#pragma unroll
        for (int t = 0; t < 4; t++) {
            int lin = tid + t * 256;
            int row = lin >> 4;
            int c8 = (lin & 15) * 8;
            *(uint4*)&Ks[row * QP + c8] = *(const uint4*)&kb[(size_t)(kt * AK + row) * HD_ + c8];
            *(uint4*)&Vs[row * QP + c8] = *(const uint4*)&vb[(size_t)(kt * AK + row) * HD_ + c8];
        }
        __syncthreads();

        float sacc[8][4];
#pragma unroll
        for (int j = 0; j < 8; j++)
#pragma unroll
            for (int c = 0; c < 4; c++)
                sacc[j][c] = 0.f;

#pragma unroll
        for (int kk = 0; kk < HD_; kk += 16) {
            unsigned afr[4];
            ldm_x4(afr, &Qs[(wid * 16 + (lane & 15)) * QP + kk + (lane >> 4) * 8]);
#pragma unroll
            for (int j = 0; j < 4; j++) {
                unsigned bfr[4];
                ldm_x4(bfr, &Ks[(j * 16 + (lane >> 4) * 8 + (lane & 7)) * QP + kk + ((lane >> 3) & 1) * 8]);
                mma16816(sacc[2 * j], afr, bfr[0], bfr[1]);
                mma16816(sacc[2 * j + 1], afr, bfr[2], bfr[3]);
            }
        }

#pragma unroll
        for (int j = 0; j < 8; j++) {
            int kg = kt * AK + j * 8 + (lane & 3) * 2;
            if (row0 < 4 * kg + 3) sacc[j][0] = -1e30f;
            if (row0 < 4 * kg + 7) sacc[j][1] = -1e30f;
            if (row1 < 4 * kg + 3) sacc[j][2] = -1e30f;
            if (row1 < 4 * kg + 7) sacc[j][3] = -1e30f;
        }

        float mx0 = -1e30f, mx1 = -1e30f;
#pragma unroll
        for (int j = 0; j < 8; j++) {
            mx0 = fmaxf(mx0, fmaxf(sacc[j][0], sacc[j][1]));
            mx1 = fmaxf(mx1, fmaxf(sacc[j][2], sacc[j][3]));
        }
        mx0 = fmaxf(mx0, __shfl_xor_sync(0xffffffffu, mx0, 1));
        mx0 = fmaxf(mx0, __shfl_xor_sync(0xffffffffu, mx0, 2));
        mx1 = fmaxf(mx1, __shfl_xor_sync(0xffffffffu, mx1, 1));
        mx1 = fmaxf(mx1, __shfl_xor_sync(0xffffffffu, mx1, 2));

        float mn0 = fmaxf(m0, mx0);
        float mn1 = fmaxf(m1, mx1);
        float sc0 = __expf(m0 - mn0);
        float sc1 = __expf(m1 - mn1);
        m0 = mn0;
        m1 = mn1;

        unsigned ph[8][2];
        float rs0 = 0.f, rs1 = 0.f;
#pragma unroll
        for (int j = 0; j < 8; j++) {
            float p00 = __expf(sacc[j][0] - m0);
            float p01 = __expf(sacc[j][1] - m0);
            float p10 = __expf(sacc[j][2] - m1);
            float p11 = __expf(sacc[j][3] - m1);
            rs0 += p00 + p01;
            rs1 += p10 + p11;
            __half2 h0 = __floats2half2_rn(p00, p01);
            __half2 h1 = __floats2half2_rn(p10, p11);
            ph[j][0] = *reinterpret_cast<unsigned*>(&h0);
            ph[j][1] = *reinterpret_cast<unsigned*>(&h1);
        }
        rs0 += __shfl_xor_sync(0xffffffffu, rs0, 1);
        rs0 += __shfl_xor_sync(0xffffffffu, rs0, 2);
        rs1 += __shfl_xor_sync(0xffffffffu, rs1, 1);
        rs1 += __shfl_xor_sync(0xffffffffu, rs1, 2);
        l0 = l0 * sc0 + rs0;
        l1 = l1 * sc1 + rs1;

#pragma unroll
        for (int j = 0; j < 16; j++) {
            oacc[j][0] *= sc0;
            oacc[j][1] *= sc0;
            oacc[j][2] *= sc1;
            oacc[j][3] *= sc1;
        }

#pragma unroll
        for (int c = 0; c < 4; c++) {
            unsigned pa[4];
            pa[0] = ph[2 * c][0];
            pa[1] = ph[2 * c][1];
            pa[2] = ph[2 * c + 1][0];
            pa[3] = ph[2 * c + 1][1];
#pragma unroll
            for (int j = 0; j < 8; j++) {
                unsigned bfr[4];
                ldm_x4_t(bfr, &Vs[(c * 16 + ((lane >> 3) & 1) * 8 + (lane & 7)) * QP + j * 16 + (lane >> 4) * 8]);
                mma16816(oacc[2 * j], pa, bfr[0], bfr[1]);
                mma16816(oacc[2 * j + 1], pa, bfr[2], bfr[3]);
            }
        }
    }

    float sh = sinks[h];
    float mf0 = fmaxf(m0, sh);
    float mf1 = fmaxf(m1, sh);
    float lf0 = l0 * __expf(m0 - mf0) + __expf(sh - mf0);
    float lf1 = l1 * __expf(m1 - mf1) + __expf(sh - mf1);
    float fs0 = __expf(m0 - mf0) / lf0;
    float fs1 = __expf(m1 - mf1) / lf1;

    __half* ob = (__half*)g_h_attn;
    size_t base0 = ((size_t)b * S_ + row0) * QN_ + h * HD_ + (lane & 3) * 2;
    size_t base1 = ((size_t)b * S_ + row1) * QN_ + h * HD_ + (lane & 3) * 2;
#pragma unroll
    for (int j = 0; j < 16; j++) {
        __half2 w0 = __floats2half2_rn(oacc[j][0] * fs0, oacc[j][1] * fs0);
        __half2 w1 = __floats2half2_rn(oacc[j][2] * fs1, oacc[j][3] * fs1);
        *(__half2*)&ob[base0 + j * 8] = w0;
        *(__half2*)&ob[base1 + j * 8] = w1;
    }
}

// ---------------- launch ----------------
extern "C" void kernel_launch(void* const* d_in, const int* in_sizes, int n_in,
                              void* d_out, int out_size)
{
    const float* hidden = (const float*)d_in[0];
    const float* wq = (const float*)d_in[1];
    const float* wkv = (const float*)d_in[2];
    const float* wgate = (const float*)d_in[3];
    const float* ape = (const float*)d_in[4];
    const float* sinks = (const float*)d_in[5];
    const float* wo = (const float*)d_in[6];
    float* out = (float*)d_out;

    void* p_qkvg = 0;
    void* p_hh = 0;
    void* p_hwf = 0;
    void* p_hwo = 0;
    void* p_hattn = 0;
    cudaGetSymbolAddress(&p_qkvg, g_qkvg);
    cudaGetSymbolAddress(&p_hh, g_h_hidden);
    cudaGetSymbolAddress(&p_hwf, g_h_wfused);
    cudaGetSymbolAddress(&p_hwo, g_h_wo);
    cudaGetSymbolAddress(&p_hattn, g_h_attn);

    int n4a = (int)((size_t)MS_ * HID_ / 4);
    f2h_kernel<<<(n4a + 255) / 256, 256>>>((const float4*)hidden, (__half2*)p_hh, n4a);

    int npack = HID_ * QKVN;
    pack_w_kernel<<<(npack + 255) / 256, 256>>>(wq, wkv, wgate, (__half*)p_hwf);

    int n4d = (int)((size_t)QN_ * HID_ / 4);
    f2h_kernel<<<(n4d + 255) / 256, 256>>>((const float4*)wo, (__half2*)p_hwo, n4d);

    cudaFuncSetAttribute(hgemm, cudaFuncAttributeMaxDynamicSharedMemorySize, HG_SMEM);

    // fused q | kv | gate projection
    hgemm<<<dim3(QKVN / GBN, MS_ / GBM), 256, HG_SMEM>>>(
        (const __half*)p_hh, (const __half*)p_hwf, (float*)p_qkvg, MS_, QKVN, HID_);

    pool_kernel<<<(B_ * NW_ * 64 + 255) / 256, 256>>>(ape);
    rope_q_kernel<<<(MS_ * NH_ * 64 + 255) / 256, 256>>>();

    size_t shmem = (size_t)(AQ + 2 * AK) * QP * sizeof(__half);
    cudaFuncSetAttribute(attn_mma_kernel, cudaFuncAttributeMaxDynamicSharedMemorySize, (int)shmem);
    attn_mma_kernel<<<dim3(S_ / AQ, NH_, B_), 256, shmem>>>(sinks);

    hgemm<<<dim3(HID_ / GBN, MS_ / GBM), 256, HG_SMEM>>>(
        (const __half*)p_hattn, (const __half*)p_hwo, out, MS_, HID_, QN_);
}

// round 8
// speedup vs baseline: 4.7279x; 1.0111x over previous
#include <cuda_runtime.h>
#include <cuda_fp16.h>
#include <math.h>

#define B_     2
#define S_     4096
#define HID_   2048
#define NH_    16
#define HD_    128
#define RATIO_ 4
#define NW_    1024
#define MS_    8192
#define QN_    2048
#define QKVN   2560   /* fused q(2048) | kv(256) | gate(256) */

#define AQ  128
#define AK  64
#define QP  136

#define GBM 128
#define GBN 128
#define GBK 32
#define ASTR 40
#define BSTR 136
#define ASTAGE (GBM * ASTR)
#define BSTAGE (GBK * BSTR)
#define NSTAGE 3
#define HG_SMEM ((NSTAGE * (ASTAGE + BSTAGE)) * 2)

/* attention smem: Q[AQ][QP] + K[2][AK][QP] + V[2][AK][QP] */
#define AT_SMEM ((AQ * QP + 4 * AK * QP) * 2)

// ---------------- scratch (static device allocations) ----------------
__device__ float g_qkvg[(size_t)MS_ * QKVN];

__device__ unsigned short g_h_hidden[(size_t)MS_ * HID_];
__device__ unsigned short g_h_wfused[(size_t)HID_ * QKVN];
__device__ unsigned short g_h_wo[(size_t)QN_ * HID_];
__device__ unsigned short g_h_attn[(size_t)MS_ * QN_];
__device__ unsigned short g_h_qrot[(size_t)MS_ * QN_];
__device__ unsigned short g_h_krot[(size_t)B_ * NW_ * HD_];
__device__ unsigned short g_h_v[(size_t)B_ * NW_ * HD_];

// ---------------- fp32 -> fp16 (plain) ----------------
__global__ void f2h_kernel(const float4* __restrict__ in, __half2* __restrict__ out, int n4)
{
    int i = blockIdx.x * blockDim.x + threadIdx.x;
    if (i < n4) {
        float4 v = in[i];
        out[2 * i] = __floats2half2_rn(v.x, v.y);
        out[2 * i + 1] = __floats2half2_rn(v.z, v.w);
    }
}

// ---------------- pack wq|wkv|wgate -> fp16 [HID][QKVN] ----------------
__global__ void pack_w_kernel(const float* __restrict__ wq, const float* __restrict__ wkv,
                              const float* __restrict__ wgate, __half* __restrict__ dst)
{
    int idx = blockIdx.x * blockDim.x + threadIdx.x;
    if (idx >= HID_ * QKVN) return;
    int k = idx / QKVN;
    int n = idx % QKVN;
    float v;
    if (n < QN_) {
        v = wq[(size_t)k * QN_ + n];
    } else if (n < QN_ + 256) {
        v = wkv[(size_t)k * 256 + (n - QN_)];
    } else {
        v = wgate[(size_t)k * 256 + (n - QN_ - 256)];
    }
    dst[idx] = __float2half(v);
}

// ---------------- PTX helpers ----------------
__device__ __forceinline__ unsigned su32(const void* p)
{
    return (unsigned)__cvta_generic_to_shared(p);
}

__device__ __forceinline__ void cp16(void* dst, const void* src)
{
    unsigned d = su32(dst);
    asm volatile("cp.async.cg.shared.global [%0], [%1], 16;" :: "r"(d), "l"(src));
}

__device__ __forceinline__ void cp_commit()
{
    asm volatile("cp.async.commit_group;");
}

__device__ __forceinline__ void cp_wait1()
{
    asm volatile("cp.async.wait_group 1;");
}

__device__ __forceinline__ void cp_wait0()
{
    asm volatile("cp.async.wait_group 0;");
}

__device__ __forceinline__ void ldm_x4(unsigned* r, const void* p)
{
    unsigned a = su32(p);
    asm volatile("ldmatrix.sync.aligned.m8n8.x4.shared.b16 {%0,%1,%2,%3}, [%4];"
                 : "=r"(r[0]), "=r"(r[1]), "=r"(r[2]), "=r"(r[3]) : "r"(a));
}

__device__ __forceinline__ void ldm_x4_t(unsigned* r, const void* p)
{
    unsigned a = su32(p);
    asm volatile("ldmatrix.sync.aligned.m8n8.x4.trans.shared.b16 {%0,%1,%2,%3}, [%4];"
                 : "=r"(r[0]), "=r"(r[1]), "=r"(r[2]), "=r"(r[3]) : "r"(a));
}

__device__ __forceinline__ void mma16816(float* c, const unsigned* a, unsigned b0, unsigned b1)
{
    asm volatile("mma.sync.aligned.m16n8k16.row.col.f32.f16.f16.f32 "
                 "{%0,%1,%2,%3},{%4,%5,%6,%7},{%8,%9},{%0,%1,%2,%3};"
                 : "+f"(c[0]), "+f"(c[1]), "+f"(c[2]), "+f"(c[3])
                 : "r"(a[0]), "r"(a[1]), "r"(a[2]), "r"(a[3]), "r"(b0), "r"(b1));
}

// ---------------- 128x128x32, 3-stage pipelined fp16 HGEMM ----------------
__global__ __launch_bounds__(256, 2) void hgemm(
    const __half* __restrict__ A, const __half* __restrict__ Bm,
    float* __restrict__ C, int M, int N, int K)
{
    extern __shared__ __half hsm[];
    __half* As = hsm;
    __half* Bs = hsm + NSTAGE * ASTAGE;

    int tid = threadIdx.x;
    int lane = tid & 31;
    int wid = tid >> 5;
    int warpM = wid & 3;
    int warpN = wid >> 2;
    int rowBase = blockIdx.y * GBM;
    int colBase = blockIdx.x * GBN;

    float acc[2][8][4];
#pragma unroll
    for (int i = 0; i < 2; i++)
#pragma unroll
        for (int j = 0; j < 8; j++)
#pragma unroll
            for (int c = 0; c < 4; c++)
                acc[i][j][c] = 0.f;

    int arow = tid >> 2;
    int acol = (tid & 3) * 8;
    int brow = tid >> 4;
    int bcol = (tid & 15) * 8;

    const __half* Ag0 = A + (size_t)(rowBase + arow) * K + acol;
    const __half* Bg0 = Bm + (size_t)brow * N + colBase + bcol;

    int T = K / GBK;

#pragma unroll
    for (int s = 0; s < 2; s++) {
        const __half* Ag = Ag0 + (size_t)s * GBK;
        const __half* Bg = Bg0 + (size_t)s * GBK * N;
        cp16(&As[s * ASTAGE + arow * ASTR + acol], Ag);
        cp16(&As[s * ASTAGE + (arow + 64) * ASTR + acol], Ag + (size_t)64 * K);
        cp16(&Bs[s * BSTAGE + brow * BSTR + bcol], Bg);
        cp16(&Bs[s * BSTAGE + (brow + 16) * BSTR + bcol], Bg + (size_t)16 * N);
        cp_commit();
    }

    for (int t = 0; t < T; t++) {
        if (t < T - 1) {
            cp_wait1();
        } else {
            cp_wait0();
        }
        __syncthreads();

        if (t + 2 < T) {
            int so = (t + 2) % NSTAGE;
            const __half* Ag = Ag0 + (size_t)(t + 2) * GBK;
            const __half* Bg = Bg0 + (size_t)(t + 2) * GBK * N;
            cp16(&As[so * ASTAGE + arow * ASTR + acol], Ag);
            cp16(&As[so * ASTAGE + (arow + 64) * ASTR + acol], Ag + (size_t)64 * K);
            cp16(&Bs[so * BSTAGE + brow * BSTR + bcol], Bg);
            cp16(&Bs[so * BSTAGE + (brow + 16) * BSTR + bcol], Bg + (size_t)16 * N);
            cp_commit();
        }

        int s = t % NSTAGE;
        const __half* Asb = &As[s * ASTAGE];
        const __half* Bsb = &Bs[s * BSTAGE];
#pragma unroll
        for (int kk = 0; kk < GBK; kk += 16) {
            unsigned afr[2][4];
            unsigned bfr[4][4];
#pragma unroll
            for (int i = 0; i < 2; i++) {
                ldm_x4(afr[i], &Asb[(warpM * 32 + i * 16 + (lane & 15)) * ASTR + kk + (lane >> 4) * 8]);
            }
#pragma unroll
            for (int j = 0; j < 4; j++) {
                ldm_x4_t(bfr[j], &Bsb[(kk + ((lane >> 3) & 1) * 8 + (lane & 7)) * BSTR + warpN * 64 + j * 16 + (lane >> 4) * 8]);
            }
#pragma unroll
            for (int i = 0; i < 2; i++) {
#pragma unroll
                for (int j = 0; j < 4; j++) {
                    mma16816(acc[i][2 * j], afr[i], bfr[j][0], bfr[j][1]);
                    mma16816(acc[i][2 * j + 1], afr[i], bfr[j][2], bfr[j][3]);
                }
            }
        }
    }

    int r0 = rowBase + warpM * 32 + (lane >> 2);
    int c0 = colBase + warpN * 64 + (lane & 3) * 2;
#pragma unroll
    for (int i = 0; i < 2; i++) {
#pragma unroll
        for (int j = 0; j < 8; j++) {
            float2* p0 = (float2*)&C[(size_t)(r0 + i * 16) * N + c0 + j * 8];
            p0[0] = make_float2(acc[i][j][0], acc[i][j][1]);
            float2* p1 = (float2*)&C[(size_t)(r0 + i * 16 + 8) * N + c0 + j * 8];
            p1[0] = make_float2(acc[i][j][2], acc[i][j][3]);
        }
    }
}

// ---------------- overlap-pool + K-RoPE (reads fused qkvg buffer) ----------------
__global__ void pool_kernel(const float* __restrict__ ape)
{
    int idx = blockIdx.x * blockDim.x + threadIdx.x;
    if (idx >= B_ * NW_ * 64) return;
    int p = idx & 63;
    int w = (idx >> 6) % NW_;
    int b = idx / (64 * NW_);
    int d0 = 2 * p;

    const float* base = g_qkvg + (size_t)b * S_ * QKVN;

    float kvv[8][2];
    float gv[8][2];
#pragma unroll
    for (int j = 0; j < RATIO_; j++) {
        if (w > 0) {
            int t = (w - 1) * RATIO_ + j;
            const float* rowp = base + (size_t)t * QKVN;
            float2 kk = *(const float2*)&rowp[QN_ + d0];
            float2 gg = *(const float2*)&rowp[QN_ + 256 + d0];
            float2 aa = *(const float2*)&ape[(size_t)j * 2 * HD_ + d0];
            kvv[j][0] = kk.x;
            kvv[j][1] = kk.y;
            gv[j][0] = gg.x + aa.x;
            gv[j][1] = gg.y + aa.y;
        } else {
            kvv[j][0] = 0.f;
            kvv[j][1] = 0.f;
            gv[j][0] = -1e30f;
            gv[j][1] = -1e30f;
        }
        int t2 = w * RATIO_ + j;
        const float* rowp2 = base + (size_t)t2 * QKVN;
        float2 kk2 = *(const float2*)&rowp2[QN_ + HD_ + d0];
        float2 gg2 = *(const float2*)&rowp2[QN_ + 256 + HD_ + d0];
        float2 aa2 = *(const float2*)&ape[(size_t)j * 2 * HD_ + HD_ + d0];
        kvv[4 + j][0] = kk2.x;
        kvv[4 + j][1] = kk2.y;
        gv[4 + j][0] = gg2.x + aa2.x;
        gv[4 + j][1] = gg2.y + aa2.y;
    }

    float out2[2];
#pragma unroll
    for (int c = 0; c < 2; c++) {
        float m = -1e30f;
#pragma unroll
        for (int j = 0; j < 8; j++) m = fmaxf(m, gv[j][c]);
        float s = 0.f;
        float acc = 0.f;
#pragma unroll
        for (int j = 0; j < 8; j++) {
            float e = __expf(gv[j][c] - m);
            s += e;
            acc += e * kvv[j][c];
        }
        out2[c] = acc / s;
    }

    __half2* vp = (__half2*)((__half*)g_h_v + ((size_t)b * NW_ + w) * HD_ + d0);
    vp[0] = __floats2half2_rn(out2[0], out2[1]);

    float y0 = out2[0];
    float y1 = out2[1];
    if (p >= 32) {
        int i = p - 32;
        float inv = (float)pow(10000.0, -(double)i / 32.0);
        float ang = (float)(w * RATIO_) * inv;
        float sn, cs;
        sincosf(ang, &sn, &cs);
        y0 = out2[0] * cs - out2[1] * sn;
        y1 = out2[0] * sn + out2[1] * cs;
    }
    __half2* kp = (__half2*)((__half*)g_h_krot + ((size_t)b * NW_ + w) * HD_ + d0);
    kp[0] = __floats2half2_rn(y0, y1);
}

// ---------------- Q RoPE + transpose, pre-scaled, fp16 out ----------------
__global__ void rope_q_kernel()
{
    int idx = blockIdx.x * blockDim.x + threadIdx.x;
    if (idx >= MS_ * NH_ * 64) return;
    int p = idx & 63;
    int h = (idx >> 6) % NH_;
    int bs = idx / (64 * NH_);
    int b = bs / S_;
    int s = bs % S_;

    const float2 xv = *(const float2*)(g_qkvg + (size_t)bs * QKVN + h * HD_ + 2 * p);
    float y0 = xv.x;
    float y1 = xv.y;
    if (p >= 32) {
        int i = p - 32;
        float inv = (float)pow(10000.0, -(double)i / 32.0);
        float ang = (float)s * inv;
        float sn, cs;
        sincosf(ang, &sn, &cs);
        y0 = xv.x * cs - xv.y * sn;
        y1 = xv.x * sn + xv.y * cs;
    }
    const float scale = 0.08838834764831845f;
    __half2* dst = (__half2*)((__half*)g_h_qrot + (((size_t)b * NH_ + h) * S_ + s) * HD_ + 2 * p);
    dst[0] = __floats2half2_rn(y0 * scale, y1 * scale);
}

// ---------------- tensor-core flash attention with sink, pipelined K/V ----------------
__global__ __launch_bounds__(256, 1) void attn_mma_kernel(const float* __restrict__ sinks)
{
    extern __shared__ __half smh[];
    __half* Qs = smh;                              // [AQ][QP]
    __half* Kb[2];
    __half* Vb[2];
    Kb[0] = Qs + AQ * QP;
    Vb[0] = Kb[0] + AK * QP;
    Kb[1] = Vb[0] + AK * QP;
    Vb[1] = Kb[1] + AK * QP;

    int tid = threadIdx.x;
    int lane = tid & 31;
    int wid = tid >> 5;
    int b = blockIdx.z;
    int h = blockIdx.y;
    int q0 = blockIdx.x * AQ;

    // load Q tile
    const __half* qsrc = (const __half*)g_h_qrot + (((size_t)b * NH_ + h) * S_ + q0) * HD_;
#pragma unroll
    for (int t = 0; t < 8; t++) {
        int lin = tid + t * 256;
        int row = lin >> 4;
        int c8 = (lin & 15) * 8;
        *(uint4*)&Qs[row * QP + c8] = *(const uint4*)&qsrc[(size_t)row * HD_ + c8];
    }
    __syncthreads();

    // preload Q fragments into registers (8 k16-chunks)
    unsigned qfr[8][4];
#pragma unroll
    for (int kk8 = 0; kk8 < 8; kk8++) {
        ldm_x4(qfr[kk8], &Qs[(wid * 16 + (lane & 15)) * QP + kk8 * 16 + (lane >> 4) * 8]);
    }

    float m0 = -1e30f, m1 = -1e30f;
    float l0 = 0.f, l1 = 0.f;
    float oacc[16][4];
#pragma unroll
    for (int j = 0; j < 16; j++)
#pragma unroll
        for (int c = 0; c < 4; c++)
            oacc[j][c] = 0.f;

    int kmax = (q0 + AQ - 4) >> 2;
    if (kmax > NW_ - 1) kmax = NW_ - 1;
    int nkt = kmax / AK + 1;

    const __half* kb = (const __half*)g_h_krot + (size_t)b * NW_ * HD_;
    const __half* vb = (const __half*)g_h_v + (size_t)b * NW_ * HD_;

    int row0 = q0 + wid * 16 + (lane >> 2);
    int row1 = row0 + 8;

    int ldrow = tid >> 4;          // 0..15
    int ldc8 = (tid & 15) * 8;

    // prologue: tile 0 -> buf 0
#pragma unroll
    for (int t = 0; t < 4; t++) {
        int row = ldrow + t * 16;
        cp16(&Kb[0][row * QP + ldc8], &kb[(size_t)row * HD_ + ldc8]);
        cp16(&Vb[0][row * QP + ldc8], &vb[(size_t)row * HD_ + ldc8]);
    }
    cp_commit();

    for (int kt = 0; kt < nkt; kt++) {
        cp_wait0();
        __syncthreads();

        if (kt + 1 < nkt) {
            int so = (kt + 1) & 1;
            const __half* kn = kb + (size_t)(kt + 1) * AK * HD_;
            const __half* vn = vb + (size_t)(kt + 1) * AK * HD_;
#pragma unroll
            for (int t = 0; t < 4; t++) {
                int row = ldrow + t * 16;
                cp16(&Kb[so][row * QP + ldc8], &kn[(size_t)row * HD_ + ldc8]);
                cp16(&Vb[so][row * QP + ldc8], &vn[(size_t)row * HD_ + ldc8]);
            }
            cp_commit();
        }

        const __half* Ks = Kb[kt & 1];
        const __half* Vs = Vb[kt & 1];

        // ---- S = Q K^T ----
        float sacc[8][4];
#pragma unroll
        for (int j = 0; j < 8; j++)
#pragma unroll
            for (int c = 0; c < 4; c++)
                sacc[j][c] = 0.f;

#pragma unroll
        for (int kk8 = 0; kk8 < 8; kk8++) {
#pragma unroll
            for (int j = 0; j < 4; j++) {
                unsigned bfr[4];
                ldm_x4(bfr, &Ks[(j * 16 + (lane >> 4) * 8 + (lane & 7)) * QP + kk8 * 16 + ((lane >> 3) & 1) * 8]);
                mma16816(sacc[2 * j], qfr[kk8], bfr[0], bfr[1]);
                mma16816(sacc[2 * j + 1], qfr[kk8], bfr[2], bfr[3]);
            }
        }

        // ---- mask ----
#pragma unroll
        for (int j = 0; j < 8; j++) {
            int kg = kt * AK + j * 8 + (lane & 3) * 2;
            if (row0 < 4 * kg + 3) sacc[j][0] = -1e30f;
            if (row0 < 4 * kg + 7) sacc[j][1] = -1e30f;
            if (row1 < 4 * kg + 3) sacc[j][2] = -1e30f;
            if (row1 < 4 * kg + 7) sacc[j][3] = -1e30f;
        }

        // ---- online softmax ----
        float mx0 = -1e30f, mx1 = -1e30f;
#pragma unroll
        for (int j = 0; j < 8; j++) {
            mx0 = fmaxf(mx0, fmaxf(sacc[j][0], sacc[j][1]));
            mx1 = fmaxf(mx1, fmaxf(sacc[j][2], sacc[j][3]));
        }
        mx0 = fmaxf(mx0, __shfl_xor_sync(0xffffffffu, mx0, 1));
        mx0 = fmaxf(mx0, __shfl_xor_sync(0xffffffffu, mx0, 2));
        mx1 = fmaxf(mx1, __shfl_xor_sync(0xffffffffu, mx1, 1));
        mx1 = fmaxf(mx1, __shfl_xor_sync(0xffffffffu, mx1, 2));

        float mn0 = fmaxf(m0, mx0);
        float mn1 = fmaxf(m1, mx1);
        float sc0 = __expf(m0 - mn0);
        float sc1 = __expf(m1 - mn1);
        m0 = mn0;
        m1 = mn1;

        unsigned ph[8][2];
        float rs0 = 0.f, rs1 = 0.f;
#pragma unroll
        for (int j = 0; j < 8; j++) {
            float p00 = __expf(sacc[j][0] - m0);
            float p01 = __expf(sacc[j][1] - m0);
            float p10 = __expf(sacc[j][2] - m1);
            float p11 = __expf(sacc[j][3] - m1);
            rs0 += p00 + p01;
            rs1 += p10 + p11;
            __half2 h0 = __floats2half2_rn(p00, p01);
            __half2 h1 = __floats2half2_rn(p10, p11);
            ph[j][0] = *reinterpret_cast<unsigned*>(&h0);
            ph[j][1] = *reinterpret_cast<unsigned*>(&h1);
        }
        rs0 += __shfl_xor_sync(0xffffffffu, rs0, 1);
        rs0 += __shfl_xor_sync(0xffffffffu, rs0, 2);
        rs1 += __shfl_xor_sync(0xffffffffu, rs1, 1);
        rs1 += __shfl_xor_sync(0xffffffffu, rs1, 2);
        l0 = l0 * sc0 + rs0;
        l1 = l1 * sc1 + rs1;

#pragma unroll
        for (int j = 0; j < 16; j++) {
            oacc[j][0] *= sc0;
            oacc[j][1] *= sc0;
            oacc[j][2] *= sc1;
            oacc[j][3] *= sc1;
        }

        // ---- O += P V ----
#pragma unroll
        for (int c = 0; c < 4; c++) {
            unsigned pa[4];
            pa[0] = ph[2 * c][0];
            pa[1] = ph[2 * c][1];
            pa[2] = ph[2 * c + 1][0];
            pa[3] = ph[2 * c + 1][1];
#pragma unroll
            for (int j = 0; j < 8; j++) {
                unsigned bfr[4];
                ldm_x4_t(bfr, &Vs[(c * 16 + ((lane >> 3) & 1) * 8 + (lane & 7)) * QP + j * 16 + (lane >> 4) * 8]);
                mma16816(oacc[2 * j], pa, bfr[0], bfr[1]);
                mma16816(oacc[2 * j + 1], pa, bfr[2], bfr[3]);
            }
        }
        __syncthreads();
    }

    float sh = sinks[h];
    float mf0 = fmaxf(m0, sh);
    float mf1 = fmaxf(m1, sh);
    float lf0 = l0 * __expf(m0 - mf0) + __expf(sh - mf0);
    float lf1 = l1 * __expf(m1 - mf1) + __expf(sh - mf1);
    float fs0 = __expf(m0 - mf0) / lf0;
    float fs1 = __expf(m1 - mf1) / lf1;

    __half* ob = (__half*)g_h_attn;
    size_t base0 = ((size_t)b * S_ + row0) * QN_ + h * HD_ + (lane & 3) * 2;
    size_t base1 = ((size_t)b * S_ + row1) * QN_ + h * HD_ + (lane & 3) * 2;
#pragma unroll
    for (int j = 0; j < 16; j++) {
        __half2 w0 = __floats2half2_rn(oacc[j][0] * fs0, oacc[j][1] * fs0);
        __half2 w1 = __floats2half2_rn(oacc[j][2] * fs1, oacc[j][3] * fs1);
        *(__half2*)&ob[base0 + j * 8] = w0;
        *(__half2*)&ob[base1 + j * 8] = w1;
    }
}

// ---------------- launch ----------------
extern "C" void kernel_launch(void* const* d_in, const int* in_sizes, int n_in,
                              void* d_out, int out_size)
{
    const float* hidden = (const float*)d_in[0];
    const float* wq = (const float*)d_in[1];
    const float* wkv = (const float*)d_in[2];
    const float* wgate = (const float*)d_in[3];
    const float* ape = (const float*)d_in[4];
    const float* sinks = (const float*)d_in[5];
    const float* wo = (const float*)d_in[6];
    float* out = (float*)d_out;

    void* p_qkvg = 0;
    void* p_hh = 0;
    void* p_hwf = 0;
    void* p_hwo = 0;
    void* p_hattn = 0;
    cudaGetSymbolAddress(&p_qkvg, g_qkvg);
    cudaGetSymbolAddress(&p_hh, g_h_hidden);
    cudaGetSymbolAddress(&p_hwf, g_h_wfused);
    cudaGetSymbolAddress(&p_hwo, g_h_wo);
    cudaGetSymbolAddress(&p_hattn, g_h_attn);

    int n4a = (int)((size_t)MS_ * HID_ / 4);
    f2h_kernel<<<(n4a + 255) / 256, 256>>>((const float4*)hidden, (__half2*)p_hh, n4a);

    int npack = HID_ * QKVN;
    pack_w_kernel<<<(npack + 255) / 256, 256>>>(wq, wkv, wgate, (__half*)p_hwf);

    int n4d = (int)((size_t)QN_ * HID_ / 4);
    f2h_kernel<<<(n4d + 255) / 256, 256>>>((const float4*)wo, (__half2*)p_hwo, n4d);

    cudaFuncSetAttribute(hgemm, cudaFuncAttributeMaxDynamicSharedMemorySize, HG_SMEM);

    hgemm<<<dim3(QKVN / GBN, MS_ / GBM), 256, HG_SMEM>>>(
        (const __half*)p_hh, (const __half*)p_hwf, (float*)p_qkvg, MS_, QKVN, HID_);

    pool_kernel<<<(B_ * NW_ * 64 + 255) / 256, 256>>>(ape);
    rope_q_kernel<<<(MS_ * NH_ * 64 + 255) / 256, 256>>>();

    cudaFuncSetAttribute(attn_mma_kernel, cudaFuncAttributeMaxDynamicSharedMemorySize, AT_SMEM);
    attn_mma_kernel<<<dim3(S_ / AQ, NH_, B_), 256, AT_SMEM>>>(sinks);

    hgemm<<<dim3(HID_ / GBN, MS_ / GBM), 256, HG_SMEM>>>(
        (const __half*)p_hattn, (const __half*)p_hwo, out, MS_, HID_, QN_);
}

// round 10
// speedup vs baseline: 8.8518x; 1.8723x over previous
#include <cuda_runtime.h>
#include <cuda_fp16.h>
#include <math.h>

#define B_     2
#define S_     4096
#define HID_   2048
#define NH_    16
#define HD_    128
#define RATIO_ 4
#define NW_    1024
#define MS_    8192
#define QN_    2048
#define QKVN   2560   /* fused q(2048) | kv(256) | gate(256) */

#define AQ  128
#define AK  64
#define QP  136

#define GBM 128
#define GBN 128
#define GBK 32
#define ASTR 40
#define BSTR 136
#define ASTAGE (GBM * ASTR)
#define BSTAGE (GBK * BSTR)
#define NSTAGE 3
#define HG_SMEM ((NSTAGE * (ASTAGE + BSTAGE)) * 2)

/* attention smem: Q[AQ][QP] + K[2][AK][QP] + V[2][AK][QP] */
#define AT_SMEM ((AQ * QP + 4 * AK * QP) * 2)

// ---------------- scratch (static device allocations) ----------------
__device__ float g_qkvg[(size_t)MS_ * QKVN];
__device__ float g_invfreq[32];

__device__ unsigned short g_h_hidden[(size_t)MS_ * HID_];
__device__ unsigned short g_h_wfused[(size_t)HID_ * QKVN];
__device__ unsigned short g_h_wo[(size_t)QN_ * HID_];
__device__ unsigned short g_h_attn[(size_t)MS_ * QN_];
__device__ unsigned short g_h_qrot[(size_t)MS_ * QN_];
__device__ unsigned short g_h_krot[(size_t)B_ * NW_ * HD_];
__device__ unsigned short g_h_v[(size_t)B_ * NW_ * HD_];

// ---------------- one-time inv-freq table (32 threads, exact double pow) ----------------
__global__ void init_invfreq_kernel()
{
    int i = threadIdx.x;
    if (i < 32) {
        g_invfreq[i] = (float)pow(10000.0, -(double)i / 32.0);
    }
}

// ---------------- fp32 -> fp16 (plain) ----------------
__global__ void f2h_kernel(const float4* __restrict__ in, __half2* __restrict__ out, int n4)
{
    int i = blockIdx.x * blockDim.x + threadIdx.x;
    if (i < n4) {
        float4 v = in[i];
        out[2 * i] = __floats2half2_rn(v.x, v.y);
        out[2 * i + 1] = __floats2half2_rn(v.z, v.w);
    }
}

// ---------------- pack wq|wkv|wgate -> fp16 [HID][QKVN] ----------------
__global__ void pack_w_kernel(const float* __restrict__ wq, const float* __restrict__ wkv,
                              const float* __restrict__ wgate, __half* __restrict__ dst)
{
    int idx = blockIdx.x * blockDim.x + threadIdx.x;
    if (idx >= HID_ * QKVN) return;
    int k = idx / QKVN;
    int n = idx % QKVN;
    float v;
    if (n < QN_) {
        v = wq[(size_t)k * QN_ + n];
    } else if (n < QN_ + 256) {
        v = wkv[(size_t)k * 256 + (n - QN_)];
    } else {
        v = wgate[(size_t)k * 256 + (n - QN_ - 256)];
    }
    dst[idx] = __float2half(v);
}

// ---------------- PTX helpers ----------------
__device__ __forceinline__ unsigned su32(const void* p)
{
    return (unsigned)__cvta_generic_to_shared(p);
}

__device__ __forceinline__ void cp16(void* dst, const void* src)
{
    unsigned d = su32(dst);
    asm volatile("cp.async.cg.shared.global [%0], [%1], 16;" :: "r"(d), "l"(src));
}

__device__ __forceinline__ void cp_commit()
{
    asm volatile("cp.async.commit_group;");
}

__device__ __forceinline__ void cp_wait1()
{
    asm volatile("cp.async.wait_group 1;");
}

__device__ __forceinline__ void cp_wait0()
{
    asm volatile("cp.async.wait_group 0;");
}

__device__ __forceinline__ void ldm_x4(unsigned* r, const void* p)
{
    unsigned a = su32(p);
    asm volatile("ldmatrix.sync.aligned.m8n8.x4.shared.b16 {%0,%1,%2,%3}, [%4];"
                 : "=r"(r[0]), "=r"(r[1]), "=r"(r[2]), "=r"(r[3]) : "r"(a));
}

__device__ __forceinline__ void ldm_x4_t(unsigned* r, const void* p)
{
    unsigned a = su32(p);
    asm volatile("ldmatrix.sync.aligned.m8n8.x4.trans.shared.b16 {%0,%1,%2,%3}, [%4];"
                 : "=r"(r[0]), "=r"(r[1]), "=r"(r[2]), "=r"(r[3]) : "r"(a));
}

__device__ __forceinline__ void mma16816(float* c, const unsigned* a, unsigned b0, unsigned b1)
{
    asm volatile("mma.sync.aligned.m16n8k16.row.col.f32.f16.f16.f32 "
                 "{%0,%1,%2,%3},{%4,%5,%6,%7},{%8,%9},{%0,%1,%2,%3};"
                 : "+f"(c[0]), "+f"(c[1]), "+f"(c[2]), "+f"(c[3])
                 : "r"(a[0]), "r"(a[1]), "r"(a[2]), "r"(a[3]), "r"(b0), "r"(b1));
}

// ---------------- 128x128x32, 3-stage pipelined fp16 HGEMM ----------------
__global__ __launch_bounds__(256, 2) void hgemm(
    const __half* __restrict__ A, const __half* __restrict__ Bm,
    float* __restrict__ C, int M, int N, int K)
{
    extern __shared__ __half hsm[];
    __half* As = hsm;
    __half* Bs = hsm + NSTAGE * ASTAGE;

    int tid = threadIdx.x;
    int lane = tid & 31;
    int wid = tid >> 5;
    int warpM = wid & 3;
    int warpN = wid >> 2;
    int rowBase = blockIdx.y * GBM;
    int colBase = blockIdx.x * GBN;

    float acc[2][8][4];
#pragma unroll
    for (int i = 0; i < 2; i++)
#pragma unroll
        for (int j = 0; j < 8; j++)
#pragma unroll
            for (int c = 0; c < 4; c++)
                acc[i][j][c] = 0.f;

    int arow = tid >> 2;
    int acol = (tid & 3) * 8;
    int brow = tid >> 4;
    int bcol = (tid & 15) * 8;

    const __half* Ag0 = A + (size_t)(rowBase + arow) * K + acol;
    const __half* Bg0 = Bm + (size_t)brow * N + colBase + bcol;

    int T = K / GBK;

#pragma unroll
    for (int s = 0; s < 2; s++) {
        const __half* Ag = Ag0 + (size_t)s * GBK;
        const __half* Bg = Bg0 + (size_t)s * GBK * N;
        cp16(&As[s * ASTAGE + arow * ASTR + acol], Ag);
        cp16(&As[s * ASTAGE + (arow + 64) * ASTR + acol], Ag + (size_t)64 * K);
        cp16(&Bs[s * BSTAGE + brow * BSTR + bcol], Bg);
        cp16(&Bs[s * BSTAGE + (brow + 16) * BSTR + bcol], Bg + (size_t)16 * N);
        cp_commit();
    }

    for (int t = 0; t < T; t++) {
        if (t < T - 1) {
            cp_wait1();
        } else {
            cp_wait0();
        }
        __syncthreads();

        if (t + 2 < T) {
            int so = (t + 2) % NSTAGE;
            const __half* Ag = Ag0 + (size_t)(t + 2) * GBK;
            const __half* Bg = Bg0 + (size_t)(t + 2) * GBK * N;
            cp16(&As[so * ASTAGE + arow * ASTR + acol], Ag);
            cp16(&As[so * ASTAGE + (arow + 64) * ASTR + acol], Ag + (size_t)64 * K);
            cp16(&Bs[so * BSTAGE + brow * BSTR + bcol], Bg);
            cp16(&Bs[so * BSTAGE + (brow + 16) * BSTR + bcol], Bg + (size_t)16 * N);
            cp_commit();
        }

        int s = t % NSTAGE;
        const __half* Asb = &As[s * ASTAGE];
        const __half* Bsb = &Bs[s * BSTAGE];
#pragma unroll
        for (int kk = 0; kk < GBK; kk += 16) {
            unsigned afr[2][4];
            unsigned bfr[4][4];
#pragma unroll
            for (int i = 0; i < 2; i++) {
                ldm_x4(afr[i], &Asb[(warpM * 32 + i * 16 + (lane & 15)) * ASTR + kk + (lane >> 4) * 8]);
            }
#pragma unroll
            for (int j = 0; j < 4; j++) {
                ldm_x4_t(bfr[j], &Bsb[(kk + ((lane >> 3) & 1) * 8 + (lane & 7)) * BSTR + warpN * 64 + j * 16 + (lane >> 4) * 8]);
            }
#pragma unroll
            for (int i = 0; i < 2; i++) {
#pragma unroll
                for (int j = 0; j < 4; j++) {
                    mma16816(acc[i][2 * j], afr[i], bfr[j][0], bfr[j][1]);
                    mma16816(acc[i][2 * j + 1], afr[i], bfr[j][2], bfr[j][3]);
                }
            }
        }
    }

    int r0 = rowBase + warpM * 32 + (lane >> 2);
    int c0 = colBase + warpN * 64 + (lane & 3) * 2;
#pragma unroll
    for (int i = 0; i < 2; i++) {
#pragma unroll
        for (int j = 0; j < 8; j++) {
            float2* p0 = (float2*)&C[(size_t)(r0 + i * 16) * N + c0 + j * 8];
            p0[0] = make_float2(acc[i][j][0], acc[i][j][1]);
            float2* p1 = (float2*)&C[(size_t)(r0 + i * 16 + 8) * N + c0 + j * 8];
            p1[0] = make_float2(acc[i][j][2], acc[i][j][3]);
        }
    }
}

// ---------------- overlap-pool + K-RoPE (reads fused qkvg buffer) ----------------
__global__ void pool_kernel(const float* __restrict__ ape)
{
    int idx = blockIdx.x * blockDim.x + threadIdx.x;
    if (idx >= B_ * NW_ * 64) return;
    int p = idx & 63;
    int w = (idx >> 6) % NW_;
    int b = idx / (64 * NW_);
    int d0 = 2 * p;

    const float* base = g_qkvg + (size_t)b * S_ * QKVN;

    float kvv[8][2];
    float gv[8][2];
#pragma unroll
    for (int j = 0; j < RATIO_; j++) {
        if (w > 0) {
            int t = (w - 1) * RATIO_ + j;
            const float* rowp = base + (size_t)t * QKVN;
            float2 kk = *(const float2*)&rowp[QN_ + d0];
            float2 gg = *(const float2*)&rowp[QN_ + 256 + d0];
            float2 aa = *(const float2*)&ape[(size_t)j * 2 * HD_ + d0];
            kvv[j][0] = kk.x;
            kvv[j][1] = kk.y;
            gv[j][0] = gg.x + aa.x;
            gv[j][1] = gg.y + aa.y;
        } else {
            kvv[j][0] = 0.f;
            kvv[j][1] = 0.f;
            gv[j][0] = -1e30f;
            gv[j][1] = -1e30f;
        }
        int t2 = w * RATIO_ + j;
        const float* rowp2 = base + (size_t)t2 * QKVN;
        float2 kk2 = *(const float2*)&rowp2[QN_ + HD_ + d0];
        float2 gg2 = *(const float2*)&rowp2[QN_ + 256 + HD_ + d0];
        float2 aa2 = *(const float2*)&ape[(size_t)j * 2 * HD_ + HD_ + d0];
        kvv[4 + j][0] = kk2.x;
        kvv[4 + j][1] = kk2.y;
        gv[4 + j][0] = gg2.x + aa2.x;
        gv[4 + j][1] = gg2.y + aa2.y;
    }

    float out2[2];
#pragma unroll
    for (int c = 0; c < 2; c++) {
        float m = -1e30f;
#pragma unroll
        for (int j = 0; j < 8; j++) m = fmaxf(m, gv[j][c]);
        float s = 0.f;
        float acc = 0.f;
#pragma unroll
        for (int j = 0; j < 8; j++) {
            float e = __expf(gv[j][c] - m);
            s += e;
            acc += e * kvv[j][c];
        }
        out2[c] = acc / s;
    }

    __half2* vp = (__half2*)((__half*)g_h_v + ((size_t)b * NW_ + w) * HD_ + d0);
    vp[0] = __floats2half2_rn(out2[0], out2[1]);

    float y0 = out2[0];
    float y1 = out2[1];
    if (p >= 32) {
        int i = p - 32;
        float inv = g_invfreq[i];
        float ang = (float)(w * RATIO_) * inv;
        float sn, cs;
        sincosf(ang, &sn, &cs);
        y0 = out2[0] * cs - out2[1] * sn;
        y1 = out2[0] * sn + out2[1] * cs;
    }
    __half2* kp = (__half2*)((__half*)g_h_krot + ((size_t)b * NW_ + w) * HD_ + d0);
    kp[0] = __floats2half2_rn(y0, y1);
}

// ---------------- Q RoPE + transpose, pre-scaled, fp16 out ----------------
__global__ void rope_q_kernel()
{
    int idx = blockIdx.x * blockDim.x + threadIdx.x;
    if (idx >= MS_ * NH_ * 64) return;
    int p = idx & 63;
    int h = (idx >> 6) % NH_;
    int bs = idx / (64 * NH_);
    int b = bs / S_;
    int s = bs % S_;

    const float2 xv = *(const float2*)(g_qkvg + (size_t)bs * QKVN + h * HD_ + 2 * p);
    float y0 = xv.x;
    float y1 = xv.y;
    if (p >= 32) {
        int i = p - 32;
        float inv = g_invfreq[i];
        float ang = (float)s * inv;
        float sn, cs;
        sincosf(ang, &sn, &cs);
        y0 = xv.x * cs - xv.y * sn;
        y1 = xv.x * sn + xv.y * cs;
    }
    const float scale = 0.08838834764831845f;
    __half2* dst = (__half2*)((__half*)g_h_qrot + (((size_t)b * NH_ + h) * S_ + s) * HD_ + 2 * p);
    dst[0] = __floats2half2_rn(y0 * scale, y1 * scale);
}

// ---------------- tensor-core flash attention with sink, pipelined K/V ----------------
__global__ __launch_bounds__(256, 1) void attn_mma_kernel(const float* __restrict__ sinks)
{
    extern __shared__ __half smh[];
    __half* Qs = smh;                              // [AQ][QP]
    __half* Kb[2];
    __half* Vb[2];
    Kb[0] = Qs + AQ * QP;
    Vb[0] = Kb[0] + AK * QP;
    Kb[1] = Vb[0] + AK * QP;
    Vb[1] = Kb[1] + AK * QP;

    int tid = threadIdx.x;
    int lane = tid & 31;
    int wid = tid >> 5;
    int b = blockIdx.z;
    int h = blockIdx.y;
    int q0 = blockIdx.x * AQ;

    // load Q tile
    const __half* qsrc = (const __half*)g_h_qrot + (((size_t)b * NH_ + h) * S_ + q0) * HD_;
#pragma unroll
    for (int t = 0; t < 8; t++) {
        int lin = tid + t * 256;
        int row = lin >> 4;
        int c8 = (lin & 15) * 8;
        *(uint4*)&Qs[row * QP + c8] = *(const uint4*)&qsrc[(size_t)row * HD_ + c8];
    }
    __syncthreads();

    // preload Q fragments into registers (8 k16-chunks)
    unsigned qfr[8][4];
#pragma unroll
    for (int kk8 = 0; kk8 < 8; kk8++) {
        ldm_x4(qfr[kk8], &Qs[(wid * 16 + (lane & 15)) * QP + kk8 * 16 + (lane >> 4) * 8]);
    }

    float m0 = -1e30f, m1 = -1e30f;
    float l0 = 0.f, l1 = 0.f;
    float oacc[16][4];
#pragma unroll
    for (int j = 0; j < 16; j++)
#pragma unroll
        for (int c = 0; c < 4; c++)
            oacc[j][c] = 0.f;

    int kmax = (q0 + AQ - 4) >> 2;
    if (kmax > NW_ - 1) kmax = NW_ - 1;
    int nkt = kmax / AK + 1;

    const __half* kb = (const __half*)g_h_krot + (size_t)b * NW_ * HD_;
    const __half* vb = (const __half*)g_h_v + (size_t)b * NW_ * HD_;

    int row0 = q0 + wid * 16 + (lane >> 2);
    int row1 = row0 + 8;

    int ldrow = tid >> 4;          // 0..15
    int ldc8 = (tid & 15) * 8;

    // prologue: tile 0 -> buf 0
#pragma unroll
    for (int t = 0; t < 4; t++) {
        int row = ldrow + t * 16;
        cp16(&Kb[0][row * QP + ldc8], &kb[(size_t)row * HD_ + ldc8]);
        cp16(&Vb[0][row * QP + ldc8], &vb[(size_t)row * HD_ + ldc8]);
    }
    cp_commit();

    for (int kt = 0; kt < nkt; kt++) {
        cp_wait0();
        __syncthreads();

        if (kt + 1 < nkt) {
            int so = (kt + 1) & 1;
            const __half* kn = kb + (size_t)(kt + 1) * AK * HD_;
            const __half* vn = vb + (size_t)(kt + 1) * AK * HD_;
#pragma unroll
            for (int t = 0; t < 4; t++) {
                int row = ldrow + t * 16;
                cp16(&Kb[so][row * QP + ldc8], &kn[(size_t)row * HD_ + ldc8]);
                cp16(&Vb[so][row * QP + ldc8], &vn[(size_t)row * HD_ + ldc8]);
            }
            cp_commit();
        }

        const __half* Ks = Kb[kt & 1];
        const __half* Vs = Vb[kt & 1];

        // ---- S = Q K^T ----
        float sacc[8][4];
#pragma unroll
        for (int j = 0; j < 8; j++)
#pragma unroll
            for (int c = 0; c < 4; c++)
                sacc[j][c] = 0.f;

#pragma unroll
        for (int kk8 = 0; kk8 < 8; kk8++) {
#pragma unroll
            for (int j = 0; j < 4; j++) {
                unsigned bfr[4];
                ldm_x4(bfr, &Ks[(j * 16 + (lane >> 4) * 8 + (lane & 7)) * QP + kk8 * 16 + ((lane >> 3) & 1) * 8]);
                mma16816(sacc[2 * j], qfr[kk8], bfr[0], bfr[1]);
                mma16816(sacc[2 * j + 1], qfr[kk8], bfr[2], bfr[3]);
            }
        }

        // ---- mask ----
#pragma unroll
        for (int j = 0; j < 8; j++) {
            int kg = kt * AK + j * 8 + (lane & 3) * 2;
            if (row0 < 4 * kg + 3) sacc[j][0] = -1e30f;
            if (row0 < 4 * kg + 7) sacc[j][1] = -1e30f;
            if (row1 < 4 * kg + 3) sacc[j][2] = -1e30f;
            if (row1 < 4 * kg + 7) sacc[j][3] = -1e30f;
        }

        // ---- online softmax ----
        float mx0 = -1e30f, mx1 = -1e30f;
#pragma unroll
        for (int j = 0; j < 8; j++) {
            mx0 = fmaxf(mx0, fmaxf(sacc[j][0], sacc[j][1]));
            mx1 = fmaxf(mx1, fmaxf(sacc[j][2], sacc[j][3]));
        }
        mx0 = fmaxf(mx0, __shfl_xor_sync(0xffffffffu, mx0, 1));
        mx0 = fmaxf(mx0, __shfl_xor_sync(0xffffffffu, mx0, 2));
        mx1 = fmaxf(mx1, __shfl_xor_sync(0xffffffffu, mx1, 1));
        mx1 = fmaxf(mx1, __shfl_xor_sync(0xffffffffu, mx1, 2));

        float mn0 = fmaxf(m0, mx0);
        float mn1 = fmaxf(m1, mx1);
        float sc0 = __expf(m0 - mn0);
        float sc1 = __expf(m1 - mn1);
        m0 = mn0;
        m1 = mn1;

        unsigned ph[8][2];
        float rs0 = 0.f, rs1 = 0.f;
#pragma unroll
        for (int j = 0; j < 8; j++) {
            float p00 = __expf(sacc[j][0] - m0);
            float p01 = __expf(sacc[j][1] - m0);
            float p10 = __expf(sacc[j][2] - m1);
            float p11 = __expf(sacc[j][3] - m1);
            rs0 += p00 + p01;
            rs1 += p10 + p11;
            __half2 h0 = __floats2half2_rn(p00, p01);
            __half2 h1 = __floats2half2_rn(p10, p11);
            ph[j][0] = *reinterpret_cast<unsigned*>(&h0);
            ph[j][1] = *reinterpret_cast<unsigned*>(&h1);
        }
        rs0 += __shfl_xor_sync(0xffffffffu, rs0, 1);
        rs0 += __shfl_xor_sync(0xffffffffu, rs0, 2);
        rs1 += __shfl_xor_sync(0xffffffffu, rs1, 1);
        rs1 += __shfl_xor_sync(0xffffffffu, rs1, 2);
        l0 = l0 * sc0 + rs0;
        l1 = l1 * sc1 + rs1;

#pragma unroll
        for (int j = 0; j < 16; j++) {
            oacc[j][0] *= sc0;
            oacc[j][1] *= sc0;
            oacc[j][2] *= sc1;
            oacc[j][3] *= sc1;
        }

        // ---- O += P V ----
#pragma unroll
        for (int c = 0; c < 4; c++) {
            unsigned pa[4];
            pa[0] = ph[2 * c][0];
            pa[1] = ph[2 * c][1];
            pa[2] = ph[2 * c + 1][0];
            pa[3] = ph[2 * c + 1][1];
#pragma unroll
            for (int j = 0; j < 8; j++) {
                unsigned bfr[4];
                ldm_x4_t(bfr, &Vs[(c * 16 + ((lane >> 3) & 1) * 8 + (lane & 7)) * QP + j * 16 + (lane >> 4) * 8]);
                mma16816(oacc[2 * j], pa, bfr[0], bfr[1]);
                mma16816(oacc[2 * j + 1], pa, bfr[2], bfr[3]);
            }
        }
        __syncthreads();
    }

    float sh = sinks[h];
    float mf0 = fmaxf(m0, sh);
    float mf1 = fmaxf(m1, sh);
    float lf0 = l0 * __expf(m0 - mf0) + __expf(sh - mf0);
    float lf1 = l1 * __expf(m1 - mf1) + __expf(sh - mf1);
    float fs0 = __expf(m0 - mf0) / lf0;
    float fs1 = __expf(m1 - mf1) / lf1;

    __half* ob = (__half*)g_h_attn;
    size_t base0 = ((size_t)b * S_ + row0) * QN_ + h * HD_ + (lane & 3) * 2;
    size_t base1 = ((size_t)b * S_ + row1) * QN_ + h * HD_ + (lane & 3) * 2;
#pragma unroll
    for (int j = 0; j < 16; j++) {
        __half2 w0 = __floats2half2_rn(oacc[j][0] * fs0, oacc[j][1] * fs0);
        __half2 w1 = __floats2half2_rn(oacc[j][2] * fs1, oacc[j][3] * fs1);
        *(__half2*)&ob[base0 + j * 8] = w0;
        *(__half2*)&ob[base1 + j * 8] = w1;
    }
}

// ---------------- launch ----------------
extern "C" void kernel_launch(void* const* d_in, const int* in_sizes, int n_in,
                              void* d_out, int out_size)
{
    const float* hidden = (const float*)d_in[0];
    const float* wq = (const float*)d_in[1];
    const float* wkv = (const float*)d_in[2];
    const float* wgate = (const float*)d_in[3];
    const float* ape = (const float*)d_in[4];
    const float* sinks = (const float*)d_in[5];
    const float* wo = (const float*)d_in[6];
    float* out = (float*)d_out;

    void* p_qkvg = 0;
    void* p_hh = 0;
    void* p_hwf = 0;
    void* p_hwo = 0;
    void* p_hattn = 0;
    cudaGetSymbolAddress(&p_qkvg, g_qkvg);
    cudaGetSymbolAddress(&p_hh, g_h_hidden);
    cudaGetSymbolAddress(&p_hwf, g_h_wfused);
    cudaGetSymbolAddress(&p_hwo, g_h_wo);
    cudaGetSymbolAddress(&p_hattn, g_h_attn);

    init_invfreq_kernel<<<1, 32>>>();

    int n4a = (int)((size_t)MS_ * HID_ / 4);
    f2h_kernel<<<(n4a + 255) / 256, 256>>>((const float4*)hidden, (__half2*)p_hh, n4a);

    int npack = HID_ * QKVN;
    pack_w_kernel<<<(npack + 255) / 256, 256>>>(wq, wkv, wgate, (__half*)p_hwf);

    int n4d = (int)((size_t)QN_ * HID_ / 4);
    f2h_kernel<<<(n4d + 255) / 256, 256>>>((const float4*)wo, (__half2*)p_hwo, n4d);

    cudaFuncSetAttribute(hgemm, cudaFuncAttributeMaxDynamicSharedMemorySize, HG_SMEM);

    hgemm<<<dim3(QKVN / GBN, MS_ / GBM), 256, HG_SMEM>>>(
        (const __half*)p_hh, (const __half*)p_hwf, (float*)p_qkvg, MS_, QKVN, HID_);

    pool_kernel<<<(B_ * NW_ * 64 + 255) / 256, 256>>>(ape);
    rope_q_kernel<<<(MS_ * NH_ * 64 + 255) / 256, 256>>>();

    cudaFuncSetAttribute(attn_mma_kernel, cudaFuncAttributeMaxDynamicSharedMemorySize, AT_SMEM);
    attn_mma_kernel<<<dim3(S_ / AQ, NH_, B_), 256, AT_SMEM>>>(sinks);

    hgemm<<<dim3(HID_ / GBN, MS_ / GBM), 256, HG_SMEM>>>(
        (const __half*)p_hattn, (const __half*)p_hwo, out, MS_, HID_, QN_);
}